// round 13
// baseline (speedup 1.0000x reference)
#include <cuda_runtime.h>
#include <cuda_bf16.h>
#include <stdint.h>
#include <math.h>

// ---------------------------------------------------------------------------
// NeuronBloomBlock: B=2, S=2048, D=2048, H=16, HD=128, FF=8192, fp32.
// R13 (= R12 resubmit after infra failure):
//   GEMM block tile 256x128 (256 thr, 8 warps, warp 64x64, cp.async x2).
//   Attention/LN/exp paths unchanged from R11.
// ---------------------------------------------------------------------------

#define NTOK   4096
#define DMODEL 2048
#define DQKV   6144
#define DFF    8192
#define SEQ    2048
#define NHEAD  16
#define HEADD  128
#define LNEPS  1e-5f

// scratch layout (floats)
#define OFF_H    ((size_t)0)
#define OFF_QKV  ((size_t)8388608)
#define OFF_ATTN ((size_t)(8388608 + 25165824))
#define OFF_X1   ((size_t)(8388608 + 25165824 + 8388608))
#define OFF_FF   ((size_t)(8388608 + 25165824 + 8388608 + 8388608))
#define OFF_WQKVR (OFF_FF + (size_t)33554432)
#define OFF_WOR   (OFF_WQKVR + (size_t)DMODEL * DQKV)
#define OFF_W1R   (OFF_WOR + (size_t)DMODEL * DMODEL)
#define OFF_W2R   (OFF_W1R + (size_t)DMODEL * DFF)
#define SCRATCH_FLOATS (OFF_W2R + (size_t)DFF * DMODEL)

__device__ float g_scratch[SCRATCH_FLOATS];

__device__ __forceinline__ unsigned int f2tf32(float x) {
    unsigned int y;
    asm("cvt.rna.tf32.f32 %0, %1;" : "=r"(y) : "f"(x));
    return y;
}
__device__ __forceinline__ float rtf(float x) { return __uint_as_float(f2tf32(x)); }

// exp(x) for x <= 0 via 2^t, FMA-pipe only (deg-5 poly, rel err ~2e-6).
__device__ __forceinline__ float fast_exp(float x) {
    float t = x * 1.4426950408889634f;
    t = fmaxf(t, -126.0f);
    float r = t + 12582912.0f;
    float i = r - 12582912.0f;
    float f = t - i;
    float p = 0.00133335581f;
    p = fmaf(p, f, 0.00961812910f);
    p = fmaf(p, f, 0.0555041087f);
    p = fmaf(p, f, 0.240226507f);
    p = fmaf(p, f, 0.693147180f);
    p = fmaf(p, f, 1.0f);
    float s = __int_as_float(((int)i + 127) << 23);
    return p * s;
}

__device__ __forceinline__ float gelu_fast(float v) {
    float z = fmaf(0.044715f * v, v * v, v) * 0.7978845608028654f;
    float t = z * 2.8853900817779268f;
    t = fminf(fmaxf(t, -30.0f), 30.0f);
    float r = t + 12582912.0f;
    float i = r - 12582912.0f;
    float f = t - i;
    float p = 0.00133335581f;
    p = fmaf(p, f, 0.00961812910f);
    p = fmaf(p, f, 0.0555041087f);
    p = fmaf(p, f, 0.240226507f);
    p = fmaf(p, f, 0.693147180f);
    p = fmaf(p, f, 1.0f);
    float e2z = p * __int_as_float(((int)i + 127) << 23);
    float th = 1.0f - __fdividef(2.0f, e2z + 1.0f);
    return 0.5f * v * (1.0f + th);
}

// ---------------------------------------------------------------------------
__global__ void round_kernel(const float* __restrict__ src, float* __restrict__ dst,
                             int n4) {
    int i = blockIdx.x * blockDim.x + threadIdx.x;
    int stride = gridDim.x * blockDim.x;
    for (; i < n4; i += stride) {
        float4 v = *(const float4*)(src + (size_t)i * 4);
        v.x = rtf(v.x); v.y = rtf(v.y); v.z = rtf(v.z); v.w = rtf(v.w);
        *(float4*)(dst + (size_t)i * 4) = v;
    }
}

// ---------------------------------------------------------------------------
// LayerNorm: one block per row (D=2048), 256 threads; output tf32-rounded.
// ---------------------------------------------------------------------------
__global__ void ln_kernel(const float* __restrict__ x, const float* __restrict__ w,
                          const float* __restrict__ bb, float* __restrict__ out) {
    __shared__ float red[8];
    __shared__ float stat[2];
    int row = blockIdx.x;
    int tid = threadIdx.x;
    const float* xr = x + (size_t)row * DMODEL;

    float4 a = *(const float4*)(xr + tid * 4);
    float4 b = *(const float4*)(xr + 1024 + tid * 4);

    float s = a.x + a.y + a.z + a.w + b.x + b.y + b.z + b.w;
    #pragma unroll
    for (int o = 16; o; o >>= 1) s += __shfl_xor_sync(0xffffffffu, s, o);
    if ((tid & 31) == 0) red[tid >> 5] = s;
    __syncthreads();
    if (tid < 8) {
        float t = red[tid];
        #pragma unroll
        for (int o = 4; o; o >>= 1) t += __shfl_xor_sync(0xffu, t, o);
        if (tid == 0) stat[0] = t;
    }
    __syncthreads();
    float mean = stat[0] * (1.0f / (float)DMODEL);

    float dx0 = a.x - mean, dx1 = a.y - mean, dx2 = a.z - mean, dx3 = a.w - mean;
    float dy0 = b.x - mean, dy1 = b.y - mean, dy2 = b.z - mean, dy3 = b.w - mean;
    float s2 = dx0*dx0 + dx1*dx1 + dx2*dx2 + dx3*dx3
             + dy0*dy0 + dy1*dy1 + dy2*dy2 + dy3*dy3;
    __syncthreads();
    #pragma unroll
    for (int o = 16; o; o >>= 1) s2 += __shfl_xor_sync(0xffffffffu, s2, o);
    if ((tid & 31) == 0) red[tid >> 5] = s2;
    __syncthreads();
    if (tid < 8) {
        float t = red[tid];
        #pragma unroll
        for (int o = 4; o; o >>= 1) t += __shfl_xor_sync(0xffu, t, o);
        if (tid == 0) stat[1] = t;
    }
    __syncthreads();
    float inv = rsqrtf(stat[1] * (1.0f / (float)DMODEL) + LNEPS);

    float4 w0 = *(const float4*)(w + tid * 4);
    float4 w1 = *(const float4*)(w + 1024 + tid * 4);
    float4 g0 = *(const float4*)(bb + tid * 4);
    float4 g1 = *(const float4*)(bb + 1024 + tid * 4);

    float* orow = out + (size_t)row * DMODEL;
    float4 r0, r1;
    r0.x = rtf(dx0 * inv * w0.x + g0.x); r0.y = rtf(dx1 * inv * w0.y + g0.y);
    r0.z = rtf(dx2 * inv * w0.z + g0.z); r0.w = rtf(dx3 * inv * w0.w + g0.w);
    r1.x = rtf(dy0 * inv * w1.x + g1.x); r1.y = rtf(dy1 * inv * w1.y + g1.y);
    r1.z = rtf(dy2 * inv * w1.z + g1.z); r1.w = rtf(dy3 * inv * w1.w + g1.w);
    *(float4*)(orow + tid * 4) = r0;
    *(float4*)(orow + 1024 + tid * 4) = r1;
}

// ---------------------------------------------------------------------------
// TF32 tensor-core GEMM, cp.async double-buffered.
// Block 256x128, K-tile 32, 256 threads = 8 warps (4x2), warp tile 64x64.
// ---------------------------------------------------------------------------
#define EPI_BIAS      0
#define EPI_BIAS_RES  1
#define EPI_BIAS_GELU 2

__device__ __forceinline__ void mma_tf32(float c[4],
        unsigned int a0, unsigned int a1, unsigned int a2, unsigned int a3,
        unsigned int b0, unsigned int b1) {
    asm volatile(
        "mma.sync.aligned.m16n8k8.row.col.f32.tf32.tf32.f32 "
        "{%0,%1,%2,%3}, {%4,%5,%6,%7}, {%8,%9}, {%0,%1,%2,%3};\n"
        : "+f"(c[0]), "+f"(c[1]), "+f"(c[2]), "+f"(c[3])
        : "r"(a0), "r"(a1), "r"(a2), "r"(a3), "r"(b0), "r"(b1));
}

__device__ __forceinline__ void cp16(void* smem, const void* gmem) {
    unsigned int sa = (unsigned int)__cvta_generic_to_shared(smem);
    asm volatile("cp.async.ca.shared.global [%0], [%1], 16;\n"
                 :: "r"(sa), "l"(gmem));
}
__device__ __forceinline__ void cp_commit() {
    asm volatile("cp.async.commit_group;\n");
}
template<int N>
__device__ __forceinline__ void cp_wait() {
    asm volatile("cp.async.wait_group %0;\n" :: "n"(N));
}

#define BM   256
#define APAD 36
#define BPAD 136
#define ASZ (BM * APAD)
#define BSZ (32 * BPAD)
#define GSMEM_BYTES ((2 * ASZ + 2 * BSZ) * 4)
#define AS(buf, r, k) sm[(buf) * ASZ + (r) * APAD + (k)]
#define BS(buf, r, c) sm[2 * ASZ + (buf) * BSZ + (r) * BPAD + (c)]

template<int EPI>
__global__ __launch_bounds__(256, 1)
void tgemm_kernel(const float* __restrict__ A, const float* __restrict__ W,
                  const float* __restrict__ bias, const float* __restrict__ res,
                  float* __restrict__ C, int M, int N, int K) {
    extern __shared__ float sm[];

    int tid = threadIdx.x;
    int lane = tid & 31;
    int wid  = tid >> 5;
    int warp_m = wid >> 1;          // 0..3 (64-row slab)
    int warp_n = wid & 1;           // 0..1 (64-col slab)
    int bm = blockIdx.y * BM;
    int bn = blockIdx.x * 128;

    int lr = lane >> 2;
    int lc = lane & 3;

    float acc[4][8][4];
    #pragma unroll
    for (int mt = 0; mt < 4; ++mt)
        #pragma unroll
        for (int nt = 0; nt < 8; ++nt)
            #pragma unroll
            for (int r = 0; r < 4; ++r) acc[mt][nt][r] = 0.0f;

    // loader coords: A 256x32 = 2048 float4 (8/thread); B 32x128 = 1024 (4/thread)
    int ar = tid >> 3;                 // 0..31 (stride 32 over 8 chunks)
    int ak = (tid & 7) << 2;
    int br = tid >> 5;                 // 0..7 (stride 8 over 4 chunks)
    int bc = (tid & 31) << 2;

    const float* Abase = A + (size_t)bm * K;
    const float* Wbase = W + bn;

    auto issue = [&](int stage, int buf) {
        int k0 = stage << 5;
        #pragma unroll
        for (int u = 0; u < 8; ++u) {
            int r = ar + u * 32;
            cp16(&AS(buf, r, ak), Abase + (size_t)r * K + k0 + ak);
        }
        #pragma unroll
        for (int u = 0; u < 4; ++u) {
            int r2 = br + u * 8;
            cp16(&BS(buf, r2, bc), Wbase + (size_t)(k0 + r2) * N + bc);
        }
        cp_commit();
    };

    int nk = K >> 5;
    issue(0, 0);
    issue(1, 1);

    for (int kt = 0; kt < nk; ++kt) {
        if (kt == nk - 1) cp_wait<0>(); else cp_wait<1>();
        __syncthreads();

        int cur = kt & 1;
        #pragma unroll
        for (int ks = 0; ks < 4; ++ks) {
            unsigned int af[4][4];
            #pragma unroll
            for (int mt = 0; mt < 4; ++mt) {
                int row = warp_m * 64 + mt * 16 + lr;
                int col = ks * 8 + lc;
                af[mt][0] = __float_as_uint(AS(cur, row, col));
                af[mt][1] = __float_as_uint(AS(cur, row + 8, col));
                af[mt][2] = __float_as_uint(AS(cur, row, col + 4));
                af[mt][3] = __float_as_uint(AS(cur, row + 8, col + 4));
            }
            unsigned int bf[8][2];
            #pragma unroll
            for (int nt = 0; nt < 8; ++nt) {
                int ncol = warp_n * 64 + nt * 8 + lr;
                int krow = ks * 8 + lc;
                bf[nt][0] = __float_as_uint(BS(cur, krow, ncol));
                bf[nt][1] = __float_as_uint(BS(cur, krow + 4, ncol));
            }
            #pragma unroll
            for (int mt = 0; mt < 4; ++mt)
                #pragma unroll
                for (int nt = 0; nt < 8; ++nt)
                    mma_tf32(acc[mt][nt], af[mt][0], af[mt][1], af[mt][2], af[mt][3],
                             bf[nt][0], bf[nt][1]);
        }

        if (kt + 2 < nk) {
            __syncthreads();
            issue(kt + 2, cur);
        }
    }

    #pragma unroll
    for (int mt = 0; mt < 4; ++mt) {
        int gr0 = bm + warp_m * 64 + mt * 16 + lr;
        int gr1 = gr0 + 8;
        #pragma unroll
        for (int nt = 0; nt < 8; ++nt) {
            int gc = bn + warp_n * 64 + nt * 8 + (lc << 1);
            float2 bv = *(const float2*)(bias + gc);
            float2 v0, v1;
            v0.x = acc[mt][nt][0] + bv.x; v0.y = acc[mt][nt][1] + bv.y;
            v1.x = acc[mt][nt][2] + bv.x; v1.y = acc[mt][nt][3] + bv.y;
            if (EPI == EPI_BIAS_RES) {
                float2 r0 = *(const float2*)(res + (size_t)gr0 * N + gc);
                float2 r1 = *(const float2*)(res + (size_t)gr1 * N + gc);
                v0.x += r0.x; v0.y += r0.y;
                v1.x += r1.x; v1.y += r1.y;
            }
            if (EPI == EPI_BIAS_GELU) {
                v0.x = rtf(gelu_fast(v0.x)); v0.y = rtf(gelu_fast(v0.y));
                v1.x = rtf(gelu_fast(v1.x)); v1.y = rtf(gelu_fast(v1.y));
            }
            *(float2*)(C + (size_t)gr0 * N + gc) = v0;
            *(float2*)(C + (size_t)gr1 * N + gc) = v1;
        }
    }
}

// ---------------------------------------------------------------------------
// Tensor-core flash attention (tf32 mma) with ALiBi + causal mask. (R11)
// ---------------------------------------------------------------------------
#define ATQ 128
#define QP  132
#define KP  132
#define VP  136
#define PP  68
#define AT2_SMEM ((ATQ*QP + 64*KP + 64*VP + ATQ*PP) * 4)

__global__ __launch_bounds__(256)
void attn_kernel(const float* __restrict__ qkv, float* __restrict__ out) {
    extern __shared__ float sm[];
    float* Qs = sm;
    float* Ks = Qs + ATQ * QP;
    float* Vs = Ks + 64 * KP;
    float* Ps = Vs + 64 * VP;

    int tid = threadIdx.x;
    int lane = tid & 31, w = tid >> 5;
    int lr = lane >> 2, lc = lane & 3;
    int qt = gridDim.x - 1 - blockIdx.x;
    int h = blockIdx.y, b = blockIdx.z;
    int q0 = qt * ATQ;

    const float scale = 0.08838834764831845f;
    float slope = exp2f(-0.5f * (float)(h + 1));

    const float* qbase = qkv + (size_t)b * SEQ * DQKV + (size_t)h * HEADD;
    const float* kbase = qbase + DMODEL;
    const float* vbase = qbase + 2 * DMODEL;

    for (int i = tid; i < ATQ * 32; i += 256) {
        int r = i >> 5, c4 = (i & 31) << 2;
        float4 v = *(const float4*)(qbase + (size_t)(q0 + r) * DQKV + c4);
        Qs[r * QP + c4 + 0] = rtf(v.x * scale);
        Qs[r * QP + c4 + 1] = rtf(v.y * scale);
        Qs[r * QP + c4 + 2] = rtf(v.z * scale);
        Qs[r * QP + c4 + 3] = rtf(v.w * scale);
    }

    int row0 = q0 + w * 16 + lr;
    int row1 = row0 + 8;
    int wmax = q0 + w * 16 + 15;

    float m0 = -INFINITY, m1 = -INFINITY, l0 = 0.0f, l1 = 0.0f;
    float o[16][4];
    #pragma unroll
    for (int nt = 0; nt < 16; ++nt)
        #pragma unroll
        for (int r = 0; r < 4; ++r) o[nt][r] = 0.0f;

    int nkb = 2 * qt + 2;
    for (int kb = 0; kb < nkb; ++kb) {
        int k0 = kb * 64;
        __syncthreads();
        for (int i = tid; i < 64 * 32; i += 256) {
            int r = i >> 5, c4 = (i & 31) << 2;
            float4 kv = *(const float4*)(kbase + (size_t)(k0 + r) * DQKV + c4);
            Ks[r * KP + c4 + 0] = rtf(kv.x);
            Ks[r * KP + c4 + 1] = rtf(kv.y);
            Ks[r * KP + c4 + 2] = rtf(kv.z);
            Ks[r * KP + c4 + 3] = rtf(kv.w);
            float4 vv = *(const float4*)(vbase + (size_t)(k0 + r) * DQKV + c4);
            Vs[r * VP + c4 + 0] = rtf(vv.x);
            Vs[r * VP + c4 + 1] = rtf(vv.y);
            Vs[r * VP + c4 + 2] = rtf(vv.z);
            Vs[r * VP + c4 + 3] = rtf(vv.w);
        }
        __syncthreads();
        if (k0 > wmax) continue;

        float sc[8][4];
        #pragma unroll
        for (int nt = 0; nt < 8; ++nt)
            #pragma unroll
            for (int r = 0; r < 4; ++r) sc[nt][r] = 0.0f;

        #pragma unroll
        for (int ks = 0; ks < 16; ++ks) {
            int qrow = (w * 16 + lr) * QP;
            int col = ks * 8 + lc;
            unsigned int a0 = __float_as_uint(Qs[qrow + col]);
            unsigned int a1 = __float_as_uint(Qs[qrow + 8 * QP + col]);
            unsigned int a2 = __float_as_uint(Qs[qrow + col + 4]);
            unsigned int a3 = __float_as_uint(Qs[qrow + 8 * QP + col + 4]);
            #pragma unroll
            for (int nt = 0; nt < 8; ++nt) {
                unsigned int b0 = __float_as_uint(Ks[(nt * 8 + lr) * KP + col]);
                unsigned int b1 = __float_as_uint(Ks[(nt * 8 + lr) * KP + col + 4]);
                mma_tf32(sc[nt], a0, a1, a2, a3, b0, b1);
            }
        }

        float rmax0 = -1e30f, rmax1 = -1e30f;
        #pragma unroll
        for (int nt = 0; nt < 8; ++nt) {
            int gc = k0 + nt * 8 + 2 * lc;
            float al0 = slope * (float)(gc - row0);
            float v0 = sc[nt][0] + al0;
            float v1 = sc[nt][1] + al0 + slope;
            if (gc > row0)     v0 = -1e30f;
            if (gc + 1 > row0) v1 = -1e30f;
            float al1 = slope * (float)(gc - row1);
            float u0 = sc[nt][2] + al1;
            float u1 = sc[nt][3] + al1 + slope;
            if (gc > row1)     u0 = -1e30f;
            if (gc + 1 > row1) u1 = -1e30f;
            sc[nt][0] = v0; sc[nt][1] = v1; sc[nt][2] = u0; sc[nt][3] = u1;
            rmax0 = fmaxf(rmax0, fmaxf(v0, v1));
            rmax1 = fmaxf(rmax1, fmaxf(u0, u1));
        }
        rmax0 = fmaxf(rmax0, __shfl_xor_sync(0xffffffffu, rmax0, 1));
        rmax0 = fmaxf(rmax0, __shfl_xor_sync(0xffffffffu, rmax0, 2));
        rmax1 = fmaxf(rmax1, __shfl_xor_sync(0xffffffffu, rmax1, 1));
        rmax1 = fmaxf(rmax1, __shfl_xor_sync(0xffffffffu, rmax1, 2));

        float mn0 = fmaxf(m0, rmax0), mn1 = fmaxf(m1, rmax1);
        float alpha0 = fast_exp(m0 - mn0), alpha1 = fast_exp(m1 - mn1);
        m0 = mn0; m1 = mn1;

        __syncwarp();
        float rs0 = 0.0f, rs1 = 0.0f;
        #pragma unroll
        for (int nt = 0; nt < 8; ++nt) {
            float p0 = fast_exp(sc[nt][0] - mn0);
            float p1 = fast_exp(sc[nt][1] - mn0);
            float p2 = fast_exp(sc[nt][2] - mn1);
            float p3 = fast_exp(sc[nt][3] - mn1);
            rs0 += p0 + p1; rs1 += p2 + p3;
            float2 q01; q01.x = rtf(p0); q01.y = rtf(p1);
            float2 q23; q23.x = rtf(p2); q23.y = rtf(p3);
            *(float2*)&Ps[(w * 16 + lr) * PP + nt * 8 + 2 * lc] = q01;
            *(float2*)&Ps[(w * 16 + lr + 8) * PP + nt * 8 + 2 * lc] = q23;
        }
        rs0 += __shfl_xor_sync(0xffffffffu, rs0, 1);
        rs0 += __shfl_xor_sync(0xffffffffu, rs0, 2);
        rs1 += __shfl_xor_sync(0xffffffffu, rs1, 1);
        rs1 += __shfl_xor_sync(0xffffffffu, rs1, 2);
        l0 = l0 * alpha0 + rs0;
        l1 = l1 * alpha1 + rs1;

        #pragma unroll
        for (int nt = 0; nt < 16; ++nt) {
            o[nt][0] *= alpha0; o[nt][1] *= alpha0;
            o[nt][2] *= alpha1; o[nt][3] *= alpha1;
        }
        __syncwarp();

        #pragma unroll
        for (int ks = 0; ks < 8; ++ks) {
            int prow = (w * 16 + lr) * PP;
            int col = ks * 8 + lc;
            unsigned int a0 = __float_as_uint(Ps[prow + col]);
            unsigned int a1 = __float_as_uint(Ps[prow + 8 * PP + col]);
            unsigned int a2 = __float_as_uint(Ps[prow + col + 4]);
            unsigned int a3 = __float_as_uint(Ps[prow + 8 * PP + col + 4]);
            #pragma unroll
            for (int nt = 0; nt < 16; ++nt) {
                unsigned int b0 = __float_as_uint(Vs[(col) * VP + nt * 8 + lr]);
                unsigned int b1 = __float_as_uint(Vs[(col + 4) * VP + nt * 8 + lr]);
                mma_tf32(o[nt], a0, a1, a2, a3, b0, b1);
            }
        }
    }

    float inv0 = 1.0f / l0, inv1 = 1.0f / l1;
    size_t or0 = ((size_t)(b * SEQ) + row0) * DMODEL + h * HEADD;
    size_t or1 = or0 + (size_t)8 * DMODEL;
    #pragma unroll
    for (int nt = 0; nt < 16; ++nt) {
        int c = nt * 8 + 2 * lc;
        float2 w0; w0.x = rtf(o[nt][0] * inv0); w0.y = rtf(o[nt][1] * inv0);
        float2 w1; w1.x = rtf(o[nt][2] * inv1); w1.y = rtf(o[nt][3] * inv1);
        *(float2*)(out + or0 + c) = w0;
        *(float2*)(out + or1 + c) = w1;
    }
}

// ---------------------------------------------------------------------------
extern "C" void kernel_launch(void* const* d_in, const int* in_sizes, int n_in,
                              void* d_out, int out_size) {
    const float* x     = (const float*)d_in[0];
    const float* ln1_w = (const float*)d_in[1];
    const float* ln1_b = (const float*)d_in[2];
    const float* wqkv  = (const float*)d_in[3];
    const float* bqkv  = (const float*)d_in[4];
    const float* wo    = (const float*)d_in[5];
    const float* bo    = (const float*)d_in[6];
    const float* ln2_w = (const float*)d_in[7];
    const float* ln2_b = (const float*)d_in[8];
    const float* w1    = (const float*)d_in[9];
    const float* b1    = (const float*)d_in[10];
    const float* w2    = (const float*)d_in[11];
    const float* b2    = (const float*)d_in[12];
    float* out = (float*)d_out;

    float* base = nullptr;
    cudaGetSymbolAddress((void**)&base, g_scratch);
    float* h     = base + OFF_H;
    float* qkv   = base + OFF_QKV;
    float* attn  = base + OFF_ATTN;
    float* x1    = base + OFF_X1;
    float* ff    = base + OFF_FF;
    float* wqkvr = base + OFF_WQKVR;
    float* wor   = base + OFF_WOR;
    float* w1r   = base + OFF_W1R;
    float* w2r   = base + OFF_W2R;

    cudaFuncSetAttribute(attn_kernel, cudaFuncAttributeMaxDynamicSharedMemorySize, AT2_SMEM);
    cudaFuncSetAttribute(tgemm_kernel<EPI_BIAS>,
                         cudaFuncAttributeMaxDynamicSharedMemorySize, GSMEM_BYTES);
    cudaFuncSetAttribute(tgemm_kernel<EPI_BIAS_RES>,
                         cudaFuncAttributeMaxDynamicSharedMemorySize, GSMEM_BYTES);
    cudaFuncSetAttribute(tgemm_kernel<EPI_BIAS_GELU>,
                         cudaFuncAttributeMaxDynamicSharedMemorySize, GSMEM_BYTES);

    // 0. round weights to tf32
    round_kernel<<<2048, 256>>>(wqkv, wqkvr, (DMODEL * DQKV) / 4);
    round_kernel<<<1024, 256>>>(wo,   wor,   (DMODEL * DMODEL) / 4);
    round_kernel<<<2048, 256>>>(w1,   w1r,   (DMODEL * DFF) / 4);
    round_kernel<<<2048, 256>>>(w2,   w2r,   (DFF * DMODEL) / 4);

    // 1. h = LN1(x)
    ln_kernel<<<NTOK, 256>>>(x, ln1_w, ln1_b, h);
    // 2. qkv = h @ wqkv + bqkv
    tgemm_kernel<EPI_BIAS><<<dim3(DQKV / 128, NTOK / BM), 256, GSMEM_BYTES>>>(
        h, wqkvr, bqkv, nullptr, qkv, NTOK, DQKV, DMODEL);
    // 3. attention (tensor-core)
    attn_kernel<<<dim3(SEQ / ATQ, NHEAD, 2), 256, AT2_SMEM>>>(qkv, attn);
    // 4. x1 = x + attn @ wo + bo
    tgemm_kernel<EPI_BIAS_RES><<<dim3(DMODEL / 128, NTOK / BM), 256, GSMEM_BYTES>>>(
        attn, wor, bo, x, x1, NTOK, DMODEL, DMODEL);
    // 5. h = LN2(x1)
    ln_kernel<<<NTOK, 256>>>(x1, ln2_w, ln2_b, h);
    // 6. ff = gelu(h @ w1 + b1)
    tgemm_kernel<EPI_BIAS_GELU><<<dim3(DFF / 128, NTOK / BM), 256, GSMEM_BYTES>>>(
        h, w1r, b1, nullptr, ff, NTOK, DFF, DMODEL);
    // 7. out = x1 + ff @ w2 + b2
    tgemm_kernel<EPI_BIAS_RES><<<dim3(DMODEL / 128, NTOK / BM), 256, GSMEM_BYTES>>>(
        ff, w2r, b2, x1, out, NTOK, DMODEL, DFF);
}

// round 14
// speedup vs baseline: 1.6367x; 1.6367x over previous
#include <cuda_runtime.h>
#include <cuda_bf16.h>
#include <cuda_fp16.h>
#include <stdint.h>
#include <math.h>

// ---------------------------------------------------------------------------
// NeuronBloomBlock: B=2, S=2048, D=2048, H=16, HD=128, FF=8192, fp32.
// R14: GEMMs -> fp16 mma.sync.m16n8k16 (same 10-bit mantissa as tf32, half the
//      instruction stream). Weights pre-packed to k-pair half2; activations
//      produced as fp16 by LN/attention/GELU epilogues. Attention mma stays
//      tf32 (R11). 128x128 block, 2-stage cp.async, 2 CTA/SM.
// ---------------------------------------------------------------------------

#define NTOK   4096
#define DMODEL 2048
#define DQKV   6144
#define DFF    8192
#define SEQ    2048
#define NHEAD  16
#define HEADD  128
#define LNEPS  1e-5f

// scratch layout (float units)
#define OFF_QKV   ((size_t)0)                    // fp32 [4096][6144]
#define OFF_X1    ((size_t)25165824)             // fp32 [4096][2048]
#define OFF_H     ((size_t)33554432)             // half [4096][2048]
#define OFF_ATTNH ((size_t)37748736)             // half [4096][2048]
#define OFF_FFH   ((size_t)41943040)             // half [4096][8192]
#define OFF_WQKVP ((size_t)58720256)             // half2 [1024][6144]
#define OFF_WOP   ((size_t)65011712)             // half2 [1024][2048]
#define OFF_W1P   ((size_t)67108864)             // half2 [1024][8192]
#define OFF_W2P   ((size_t)75497472)             // half2 [4096][2048]
#define SCRATCH_FLOATS ((size_t)83886080)

__device__ float g_scratch[SCRATCH_FLOATS];

__device__ __forceinline__ unsigned int f2tf32(float x) {
    unsigned int y;
    asm("cvt.rna.tf32.f32 %0, %1;" : "=r"(y) : "f"(x));
    return y;
}
__device__ __forceinline__ float rtf(float x) { return __uint_as_float(f2tf32(x)); }

// exp(x) for x <= 0 via 2^t, FMA-pipe only (deg-5 poly, rel err ~2e-6).
__device__ __forceinline__ float fast_exp(float x) {
    float t = x * 1.4426950408889634f;
    t = fmaxf(t, -126.0f);
    float r = t + 12582912.0f;
    float i = r - 12582912.0f;
    float f = t - i;
    float p = 0.00133335581f;
    p = fmaf(p, f, 0.00961812910f);
    p = fmaf(p, f, 0.0555041087f);
    p = fmaf(p, f, 0.240226507f);
    p = fmaf(p, f, 0.693147180f);
    p = fmaf(p, f, 1.0f);
    float s = __int_as_float(((int)i + 127) << 23);
    return p * s;
}

__device__ __forceinline__ float gelu_fast(float v) {
    float z = fmaf(0.044715f * v, v * v, v) * 0.7978845608028654f;
    float t = z * 2.8853900817779268f;
    t = fminf(fmaxf(t, -30.0f), 30.0f);
    float r = t + 12582912.0f;
    float i = r - 12582912.0f;
    float f = t - i;
    float p = 0.00133335581f;
    p = fmaf(p, f, 0.00961812910f);
    p = fmaf(p, f, 0.0555041087f);
    p = fmaf(p, f, 0.240226507f);
    p = fmaf(p, f, 0.693147180f);
    p = fmaf(p, f, 1.0f);
    float e2z = p * __int_as_float(((int)i + 127) << 23);
    float th = 1.0f - __fdividef(2.0f, e2z + 1.0f);
    return 0.5f * v * (1.0f + th);
}

// ---------------------------------------------------------------------------
// Weight pack: fp32 [K][N] -> half2 [K/2][N], entry = (k even, k odd).
// ---------------------------------------------------------------------------
__global__ void pack_w_kernel(const float* __restrict__ src, __half2* __restrict__ dst,
                              int K2, int N) {
    int total = K2 * (N >> 2);
    int i = blockIdx.x * blockDim.x + threadIdx.x;
    int stride = gridDim.x * blockDim.x;
    for (; i < total; i += stride) {
        int k2 = i / (N >> 2);
        int nb = (i - k2 * (N >> 2)) << 2;
        const float* r0 = src + (size_t)(2 * k2) * N + nb;
        const float* r1 = r0 + N;
        float4 a = *(const float4*)r0;
        float4 b = *(const float4*)r1;
        __half2* d = dst + (size_t)k2 * N + nb;
        d[0] = __floats2half2_rn(a.x, b.x);
        d[1] = __floats2half2_rn(a.y, b.y);
        d[2] = __floats2half2_rn(a.z, b.z);
        d[3] = __floats2half2_rn(a.w, b.w);
    }
}

// ---------------------------------------------------------------------------
// LayerNorm: one block per row (D=2048), 256 threads; output fp16.
// ---------------------------------------------------------------------------
__global__ void ln_kernel(const float* __restrict__ x, const float* __restrict__ w,
                          const float* __restrict__ bb, __half* __restrict__ out) {
    __shared__ float red[8];
    __shared__ float stat[2];
    int row = blockIdx.x;
    int tid = threadIdx.x;
    const float* xr = x + (size_t)row * DMODEL;

    float4 a = *(const float4*)(xr + tid * 4);
    float4 b = *(const float4*)(xr + 1024 + tid * 4);

    float s = a.x + a.y + a.z + a.w + b.x + b.y + b.z + b.w;
    #pragma unroll
    for (int o = 16; o; o >>= 1) s += __shfl_xor_sync(0xffffffffu, s, o);
    if ((tid & 31) == 0) red[tid >> 5] = s;
    __syncthreads();
    if (tid < 8) {
        float t = red[tid];
        #pragma unroll
        for (int o = 4; o; o >>= 1) t += __shfl_xor_sync(0xffu, t, o);
        if (tid == 0) stat[0] = t;
    }
    __syncthreads();
    float mean = stat[0] * (1.0f / (float)DMODEL);

    float dx0 = a.x - mean, dx1 = a.y - mean, dx2 = a.z - mean, dx3 = a.w - mean;
    float dy0 = b.x - mean, dy1 = b.y - mean, dy2 = b.z - mean, dy3 = b.w - mean;
    float s2 = dx0*dx0 + dx1*dx1 + dx2*dx2 + dx3*dx3
             + dy0*dy0 + dy1*dy1 + dy2*dy2 + dy3*dy3;
    __syncthreads();
    #pragma unroll
    for (int o = 16; o; o >>= 1) s2 += __shfl_xor_sync(0xffffffffu, s2, o);
    if ((tid & 31) == 0) red[tid >> 5] = s2;
    __syncthreads();
    if (tid < 8) {
        float t = red[tid];
        #pragma unroll
        for (int o = 4; o; o >>= 1) t += __shfl_xor_sync(0xffu, t, o);
        if (tid == 0) stat[1] = t;
    }
    __syncthreads();
    float inv = rsqrtf(stat[1] * (1.0f / (float)DMODEL) + LNEPS);

    float4 w0 = *(const float4*)(w + tid * 4);
    float4 w1 = *(const float4*)(w + 1024 + tid * 4);
    float4 g0 = *(const float4*)(bb + tid * 4);
    float4 g1 = *(const float4*)(bb + 1024 + tid * 4);

    __half* orow = out + (size_t)row * DMODEL;
    *(__half2*)(orow + tid * 4) =
        __floats2half2_rn(dx0 * inv * w0.x + g0.x, dx1 * inv * w0.y + g0.y);
    *(__half2*)(orow + tid * 4 + 2) =
        __floats2half2_rn(dx2 * inv * w0.z + g0.z, dx3 * inv * w0.w + g0.w);
    *(__half2*)(orow + 1024 + tid * 4) =
        __floats2half2_rn(dy0 * inv * w1.x + g1.x, dy1 * inv * w1.y + g1.y);
    *(__half2*)(orow + 1024 + tid * 4 + 2) =
        __floats2half2_rn(dy2 * inv * w1.z + g1.z, dy3 * inv * w1.w + g1.w);
}

// ---------------------------------------------------------------------------
// FP16 tensor-core GEMM: C = A(half)[M,K] @ Wpk(half2 k-pairs)[K/2,N] + bias.
// Block 128x128, K-tile 32 (2 x k16 steps), 128 threads, warp tile 64x64.
// ---------------------------------------------------------------------------
#define EPI_BIAS      0
#define EPI_BIAS_RES  1
#define EPI_GELU_H    2

__device__ __forceinline__ void mma_f16(float c[4],
        unsigned int a0, unsigned int a1, unsigned int a2, unsigned int a3,
        unsigned int b0, unsigned int b1) {
    asm volatile(
        "mma.sync.aligned.m16n8k16.row.col.f32.f16.f16.f32 "
        "{%0,%1,%2,%3}, {%4,%5,%6,%7}, {%8,%9}, {%0,%1,%2,%3};\n"
        : "+f"(c[0]), "+f"(c[1]), "+f"(c[2]), "+f"(c[3])
        : "r"(a0), "r"(a1), "r"(a2), "r"(a3), "r"(b0), "r"(b1));
}

__device__ __forceinline__ void cp16(void* smem, const void* gmem) {
    unsigned int sa = (unsigned int)__cvta_generic_to_shared(smem);
    asm volatile("cp.async.ca.shared.global [%0], [%1], 16;\n"
                 :: "r"(sa), "l"(gmem));
}
__device__ __forceinline__ void cp_commit() {
    asm volatile("cp.async.commit_group;\n");
}
template<int N>
__device__ __forceinline__ void cp_wait() {
    asm volatile("cp.async.wait_group %0;\n" :: "n"(N));
}

#define APADH 40                      // halfs per A row (80 B, conflict-free)
#define BPADH 136                     // half2 per B row (544 B, conflict-free)
#define ASZH (128 * APADH)            // halfs per A stage
#define BSZH (16 * BPADH)             // half2 per B stage
#define GSMEM_BYTES (2 * ASZH * 2 + 2 * BSZH * 4)   // 37888

template<int EPI>
__global__ __launch_bounds__(128, 2)
void hgemm_kernel(const __half* __restrict__ A, const __half2* __restrict__ Wpk,
                  const float* __restrict__ bias, const float* __restrict__ res,
                  void* __restrict__ Cv, int M, int N, int K) {
    extern __shared__ char smraw[];
    __half*  Ah  = (__half*)smraw;                       // [2][128][APADH]
    __half2* Bh2 = (__half2*)(smraw + 2 * ASZH * 2);     // [2][16][BPADH]

    int tid = threadIdx.x;
    int lane = tid & 31;
    int wid  = tid >> 5;
    int warp_m = wid >> 1;
    int warp_n = wid & 1;
    int bm = blockIdx.y * 128;
    int bn = blockIdx.x * 128;

    int lr = lane >> 2;
    int lc = lane & 3;

    float acc[4][8][4];
    #pragma unroll
    for (int mt = 0; mt < 4; ++mt)
        #pragma unroll
        for (int nt = 0; nt < 8; ++nt)
            #pragma unroll
            for (int r = 0; r < 4; ++r) acc[mt][nt][r] = 0.0f;

    const __half*  Abase = A + (size_t)bm * K;
    const __half2* Wbase = Wpk + bn;
    int N2row = N;                      // half2 entries per Wpk row

    // A: 128x32 halfs = 512 x 16B chunks (4/thread).  B: 16x128 half2 = 512 chunks.
    int ara = tid >> 2, aka = (tid & 3) << 3;      // A: row 0..31(+u*32? no: >>2 = 0..31)... see loop
    int brb = tid >> 5, bcb = (tid & 31) << 2;     // B: k2row 0..3 (stride 4), col4

    auto issue = [&](int stage, int buf) {
        int k0 = stage << 5;            // half units
        int k20 = stage << 4;           // half2 (k-pair) rows
        #pragma unroll
        for (int u = 0; u < 4; ++u) {
            int r = ara + u * 32;       // 0..127
            __half* dst = Ah + buf * ASZH + r * APADH + aka;
            cp16(dst, Abase + (size_t)r * K + k0 + aka);
        }
        #pragma unroll
        for (int u = 0; u < 4; ++u) {
            int r2 = brb + u * 4;       // 0..15
            __half2* dst = Bh2 + buf * BSZH + r2 * BPADH + bcb;
            cp16(dst, Wbase + (size_t)(k20 + r2) * N2row + bcb);
        }
        cp_commit();
    };

    int nk = K >> 5;
    issue(0, 0);
    issue(1, 1);

    for (int kt = 0; kt < nk; ++kt) {
        if (kt == nk - 1) cp_wait<0>(); else cp_wait<1>();
        __syncthreads();

        int cur = kt & 1;
        const __half*  Ac = Ah + cur * ASZH;
        const __half2* Bc = Bh2 + cur * BSZH;

        #pragma unroll
        for (int ks = 0; ks < 2; ++ks) {
            unsigned int af[4][4];
            #pragma unroll
            for (int mt = 0; mt < 4; ++mt) {
                int row = warp_m * 64 + mt * 16 + lr;
                int col = ks * 16 + 2 * lc;
                af[mt][0] = *(const unsigned int*)(Ac + row * APADH + col);
                af[mt][1] = *(const unsigned int*)(Ac + (row + 8) * APADH + col);
                af[mt][2] = *(const unsigned int*)(Ac + row * APADH + col + 8);
                af[mt][3] = *(const unsigned int*)(Ac + (row + 8) * APADH + col + 8);
            }
            unsigned int bf[8][2];
            #pragma unroll
            for (int nt = 0; nt < 8; ++nt) {
                int ncol = warp_n * 64 + nt * 8 + lr;
                int k2r = ks * 8 + lc;
                bf[nt][0] = *(const unsigned int*)(Bc + k2r * BPADH + ncol);
                bf[nt][1] = *(const unsigned int*)(Bc + (k2r + 4) * BPADH + ncol);
            }
            #pragma unroll
            for (int mt = 0; mt < 4; ++mt)
                #pragma unroll
                for (int nt = 0; nt < 8; ++nt)
                    mma_f16(acc[mt][nt], af[mt][0], af[mt][1], af[mt][2], af[mt][3],
                            bf[nt][0], bf[nt][1]);
        }

        if (kt + 2 < nk) {
            __syncthreads();
            issue(kt + 2, cur);
        }
    }

    // ---- epilogue (C layout identical to m16n8k8) ----
    #pragma unroll
    for (int mt = 0; mt < 4; ++mt) {
        int gr0 = bm + warp_m * 64 + mt * 16 + lr;
        int gr1 = gr0 + 8;
        #pragma unroll
        for (int nt = 0; nt < 8; ++nt) {
            int gc = bn + warp_n * 64 + nt * 8 + (lc << 1);
            float2 bv = *(const float2*)(bias + gc);
            float v0x = acc[mt][nt][0] + bv.x, v0y = acc[mt][nt][1] + bv.y;
            float v1x = acc[mt][nt][2] + bv.x, v1y = acc[mt][nt][3] + bv.y;
            if (EPI == EPI_BIAS_RES) {
                float2 r0 = *(const float2*)(res + (size_t)gr0 * N + gc);
                float2 r1 = *(const float2*)(res + (size_t)gr1 * N + gc);
                v0x += r0.x; v0y += r0.y;
                v1x += r1.x; v1y += r1.y;
            }
            if (EPI == EPI_GELU_H) {
                __half* Ch = (__half*)Cv;
                *(__half2*)(Ch + (size_t)gr0 * N + gc) =
                    __floats2half2_rn(gelu_fast(v0x), gelu_fast(v0y));
                *(__half2*)(Ch + (size_t)gr1 * N + gc) =
                    __floats2half2_rn(gelu_fast(v1x), gelu_fast(v1y));
            } else {
                float* Cf = (float*)Cv;
                float2 o0; o0.x = v0x; o0.y = v0y;
                float2 o1; o1.x = v1x; o1.y = v1y;
                *(float2*)(Cf + (size_t)gr0 * N + gc) = o0;
                *(float2*)(Cf + (size_t)gr1 * N + gc) = o1;
            }
        }
    }
}

// ---------------------------------------------------------------------------
// Tensor-core flash attention (tf32 mma) with ALiBi + causal mask. (R11)
// Input qkv fp32; output fp16 (feeds WO GEMM).
// ---------------------------------------------------------------------------
#define ATQ 128
#define QP  132
#define KP  132
#define VP  136
#define PP  68
#define AT2_SMEM ((ATQ*QP + 64*KP + 64*VP + ATQ*PP) * 4)

__device__ __forceinline__ void mma_tf32(float c[4],
        unsigned int a0, unsigned int a1, unsigned int a2, unsigned int a3,
        unsigned int b0, unsigned int b1) {
    asm volatile(
        "mma.sync.aligned.m16n8k8.row.col.f32.tf32.tf32.f32 "
        "{%0,%1,%2,%3}, {%4,%5,%6,%7}, {%8,%9}, {%0,%1,%2,%3};\n"
        : "+f"(c[0]), "+f"(c[1]), "+f"(c[2]), "+f"(c[3])
        : "r"(a0), "r"(a1), "r"(a2), "r"(a3), "r"(b0), "r"(b1));
}

__global__ __launch_bounds__(256)
void attn_kernel(const float* __restrict__ qkv, __half* __restrict__ out) {
    extern __shared__ float sm[];
    float* Qs = sm;
    float* Ks = Qs + ATQ * QP;
    float* Vs = Ks + 64 * KP;
    float* Ps = Vs + 64 * VP;

    int tid = threadIdx.x;
    int lane = tid & 31, w = tid >> 5;
    int lr = lane >> 2, lc = lane & 3;
    int qt = gridDim.x - 1 - blockIdx.x;
    int h = blockIdx.y, b = blockIdx.z;
    int q0 = qt * ATQ;

    const float scale = 0.08838834764831845f;
    float slope = exp2f(-0.5f * (float)(h + 1));

    const float* qbase = qkv + (size_t)b * SEQ * DQKV + (size_t)h * HEADD;
    const float* kbase = qbase + DMODEL;
    const float* vbase = qbase + 2 * DMODEL;

    for (int i = tid; i < ATQ * 32; i += 256) {
        int r = i >> 5, c4 = (i & 31) << 2;
        float4 v = *(const float4*)(qbase + (size_t)(q0 + r) * DQKV + c4);
        Qs[r * QP + c4 + 0] = rtf(v.x * scale);
        Qs[r * QP + c4 + 1] = rtf(v.y * scale);
        Qs[r * QP + c4 + 2] = rtf(v.z * scale);
        Qs[r * QP + c4 + 3] = rtf(v.w * scale);
    }

    int row0 = q0 + w * 16 + lr;
    int row1 = row0 + 8;
    int wmax = q0 + w * 16 + 15;

    float m0 = -INFINITY, m1 = -INFINITY, l0 = 0.0f, l1 = 0.0f;
    float o[16][4];
    #pragma unroll
    for (int nt = 0; nt < 16; ++nt)
        #pragma unroll
        for (int r = 0; r < 4; ++r) o[nt][r] = 0.0f;

    int nkb = 2 * qt + 2;
    for (int kb = 0; kb < nkb; ++kb) {
        int k0 = kb * 64;
        __syncthreads();
        for (int i = tid; i < 64 * 32; i += 256) {
            int r = i >> 5, c4 = (i & 31) << 2;
            float4 kv = *(const float4*)(kbase + (size_t)(k0 + r) * DQKV + c4);
            Ks[r * KP + c4 + 0] = rtf(kv.x);
            Ks[r * KP + c4 + 1] = rtf(kv.y);
            Ks[r * KP + c4 + 2] = rtf(kv.z);
            Ks[r * KP + c4 + 3] = rtf(kv.w);
            float4 vv = *(const float4*)(vbase + (size_t)(k0 + r) * DQKV + c4);
            Vs[r * VP + c4 + 0] = rtf(vv.x);
            Vs[r * VP + c4 + 1] = rtf(vv.y);
            Vs[r * VP + c4 + 2] = rtf(vv.z);
            Vs[r * VP + c4 + 3] = rtf(vv.w);
        }
        __syncthreads();
        if (k0 > wmax) continue;

        float sc[8][4];
        #pragma unroll
        for (int nt = 0; nt < 8; ++nt)
            #pragma unroll
            for (int r = 0; r < 4; ++r) sc[nt][r] = 0.0f;

        #pragma unroll
        for (int ks = 0; ks < 16; ++ks) {
            int qrow = (w * 16 + lr) * QP;
            int col = ks * 8 + lc;
            unsigned int a0 = __float_as_uint(Qs[qrow + col]);
            unsigned int a1 = __float_as_uint(Qs[qrow + 8 * QP + col]);
            unsigned int a2 = __float_as_uint(Qs[qrow + col + 4]);
            unsigned int a3 = __float_as_uint(Qs[qrow + 8 * QP + col + 4]);
            #pragma unroll
            for (int nt = 0; nt < 8; ++nt) {
                unsigned int b0 = __float_as_uint(Ks[(nt * 8 + lr) * KP + col]);
                unsigned int b1 = __float_as_uint(Ks[(nt * 8 + lr) * KP + col + 4]);
                mma_tf32(sc[nt], a0, a1, a2, a3, b0, b1);
            }
        }

        float rmax0 = -1e30f, rmax1 = -1e30f;
        #pragma unroll
        for (int nt = 0; nt < 8; ++nt) {
            int gc = k0 + nt * 8 + 2 * lc;
            float al0 = slope * (float)(gc - row0);
            float v0 = sc[nt][0] + al0;
            float v1 = sc[nt][1] + al0 + slope;
            if (gc > row0)     v0 = -1e30f;
            if (gc + 1 > row0) v1 = -1e30f;
            float al1 = slope * (float)(gc - row1);
            float u0 = sc[nt][2] + al1;
            float u1 = sc[nt][3] + al1 + slope;
            if (gc > row1)     u0 = -1e30f;
            if (gc + 1 > row1) u1 = -1e30f;
            sc[nt][0] = v0; sc[nt][1] = v1; sc[nt][2] = u0; sc[nt][3] = u1;
            rmax0 = fmaxf(rmax0, fmaxf(v0, v1));
            rmax1 = fmaxf(rmax1, fmaxf(u0, u1));
        }
        rmax0 = fmaxf(rmax0, __shfl_xor_sync(0xffffffffu, rmax0, 1));
        rmax0 = fmaxf(rmax0, __shfl_xor_sync(0xffffffffu, rmax0, 2));
        rmax1 = fmaxf(rmax1, __shfl_xor_sync(0xffffffffu, rmax1, 1));
        rmax1 = fmaxf(rmax1, __shfl_xor_sync(0xffffffffu, rmax1, 2));

        float mn0 = fmaxf(m0, rmax0), mn1 = fmaxf(m1, rmax1);
        float alpha0 = fast_exp(m0 - mn0), alpha1 = fast_exp(m1 - mn1);
        m0 = mn0; m1 = mn1;

        __syncwarp();
        float rs0 = 0.0f, rs1 = 0.0f;
        #pragma unroll
        for (int nt = 0; nt < 8; ++nt) {
            float p0 = fast_exp(sc[nt][0] - mn0);
            float p1 = fast_exp(sc[nt][1] - mn0);
            float p2 = fast_exp(sc[nt][2] - mn1);
            float p3 = fast_exp(sc[nt][3] - mn1);
            rs0 += p0 + p1; rs1 += p2 + p3;
            float2 q01; q01.x = rtf(p0); q01.y = rtf(p1);
            float2 q23; q23.x = rtf(p2); q23.y = rtf(p3);
            *(float2*)&Ps[(w * 16 + lr) * PP + nt * 8 + 2 * lc] = q01;
            *(float2*)&Ps[(w * 16 + lr + 8) * PP + nt * 8 + 2 * lc] = q23;
        }
        rs0 += __shfl_xor_sync(0xffffffffu, rs0, 1);
        rs0 += __shfl_xor_sync(0xffffffffu, rs0, 2);
        rs1 += __shfl_xor_sync(0xffffffffu, rs1, 1);
        rs1 += __shfl_xor_sync(0xffffffffu, rs1, 2);
        l0 = l0 * alpha0 + rs0;
        l1 = l1 * alpha1 + rs1;

        #pragma unroll
        for (int nt = 0; nt < 16; ++nt) {
            o[nt][0] *= alpha0; o[nt][1] *= alpha0;
            o[nt][2] *= alpha1; o[nt][3] *= alpha1;
        }
        __syncwarp();

        #pragma unroll
        for (int ks = 0; ks < 8; ++ks) {
            int prow = (w * 16 + lr) * PP;
            int col = ks * 8 + lc;
            unsigned int a0 = __float_as_uint(Ps[prow + col]);
            unsigned int a1 = __float_as_uint(Ps[prow + 8 * PP + col]);
            unsigned int a2 = __float_as_uint(Ps[prow + col + 4]);
            unsigned int a3 = __float_as_uint(Ps[prow + 8 * PP + col + 4]);
            #pragma unroll
            for (int nt = 0; nt < 16; ++nt) {
                unsigned int b0 = __float_as_uint(Vs[(col) * VP + nt * 8 + lr]);
                unsigned int b1 = __float_as_uint(Vs[(col + 4) * VP + nt * 8 + lr]);
                mma_tf32(o[nt], a0, a1, a2, a3, b0, b1);
            }
        }
    }

    float inv0 = 1.0f / l0, inv1 = 1.0f / l1;
    size_t or0 = ((size_t)(b * SEQ) + row0) * DMODEL + h * HEADD;
    size_t or1 = or0 + (size_t)8 * DMODEL;
    #pragma unroll
    for (int nt = 0; nt < 16; ++nt) {
        int c = nt * 8 + 2 * lc;
        *(__half2*)(out + or0 + c) = __floats2half2_rn(o[nt][0] * inv0, o[nt][1] * inv0);
        *(__half2*)(out + or1 + c) = __floats2half2_rn(o[nt][2] * inv1, o[nt][3] * inv1);
    }
}

// ---------------------------------------------------------------------------
extern "C" void kernel_launch(void* const* d_in, const int* in_sizes, int n_in,
                              void* d_out, int out_size) {
    const float* x     = (const float*)d_in[0];
    const float* ln1_w = (const float*)d_in[1];
    const float* ln1_b = (const float*)d_in[2];
    const float* wqkv  = (const float*)d_in[3];
    const float* bqkv  = (const float*)d_in[4];
    const float* wo    = (const float*)d_in[5];
    const float* bo    = (const float*)d_in[6];
    const float* ln2_w = (const float*)d_in[7];
    const float* ln2_b = (const float*)d_in[8];
    const float* w1    = (const float*)d_in[9];
    const float* b1    = (const float*)d_in[10];
    const float* w2    = (const float*)d_in[11];
    const float* b2    = (const float*)d_in[12];
    float* out = (float*)d_out;

    float* base = nullptr;
    cudaGetSymbolAddress((void**)&base, g_scratch);
    float*   qkv   = base + OFF_QKV;
    float*   x1    = base + OFF_X1;
    __half*  h     = (__half*)(base + OFF_H);
    __half*  attnh = (__half*)(base + OFF_ATTNH);
    __half*  ffh   = (__half*)(base + OFF_FFH);
    __half2* wqkvp = (__half2*)(base + OFF_WQKVP);
    __half2* wop   = (__half2*)(base + OFF_WOP);
    __half2* w1p   = (__half2*)(base + OFF_W1P);
    __half2* w2p   = (__half2*)(base + OFF_W2P);

    cudaFuncSetAttribute(attn_kernel, cudaFuncAttributeMaxDynamicSharedMemorySize, AT2_SMEM);
    cudaFuncSetAttribute(hgemm_kernel<EPI_BIAS>,
                         cudaFuncAttributeMaxDynamicSharedMemorySize, GSMEM_BYTES);
    cudaFuncSetAttribute(hgemm_kernel<EPI_BIAS_RES>,
                         cudaFuncAttributeMaxDynamicSharedMemorySize, GSMEM_BYTES);
    cudaFuncSetAttribute(hgemm_kernel<EPI_GELU_H>,
                         cudaFuncAttributeMaxDynamicSharedMemorySize, GSMEM_BYTES);

    // 0. pack weights to k-pair half2
    pack_w_kernel<<<2048, 256>>>(wqkv, wqkvp, DMODEL / 2, DQKV);
    pack_w_kernel<<<1024, 256>>>(wo,   wop,   DMODEL / 2, DMODEL);
    pack_w_kernel<<<2048, 256>>>(w1,   w1p,   DMODEL / 2, DFF);
    pack_w_kernel<<<2048, 256>>>(w2,   w2p,   DFF / 2,    DMODEL);

    // 1. h = LN1(x)  (fp16 out)
    ln_kernel<<<NTOK, 256>>>(x, ln1_w, ln1_b, h);
    // 2. qkv = h @ wqkv + bqkv  (fp32 out)
    hgemm_kernel<EPI_BIAS><<<dim3(DQKV / 128, NTOK / 128), 128, GSMEM_BYTES>>>(
        h, wqkvp, bqkv, nullptr, qkv, NTOK, DQKV, DMODEL);
    // 3. attention (fp16 out)
    attn_kernel<<<dim3(SEQ / ATQ, NHEAD, 2), 256, AT2_SMEM>>>(qkv, attnh);
    // 4. x1 = x + attn @ wo + bo  (fp32 out)
    hgemm_kernel<EPI_BIAS_RES><<<dim3(DMODEL / 128, NTOK / 128), 128, GSMEM_BYTES>>>(
        attnh, wop, bo, x, x1, NTOK, DMODEL, DMODEL);
    // 5. h = LN2(x1)  (fp16 out)
    ln_kernel<<<NTOK, 256>>>(x1, ln2_w, ln2_b, h);
    // 6. ff = gelu(h @ w1 + b1)  (fp16 out)
    hgemm_kernel<EPI_GELU_H><<<dim3(DFF / 128, NTOK / 128), 128, GSMEM_BYTES>>>(
        h, w1p, b1, nullptr, ffh, NTOK, DFF, DMODEL);
    // 7. out = x1 + ff @ w2 + b2  (fp32 out)
    hgemm_kernel<EPI_BIAS_RES><<<dim3(DMODEL / 128, NTOK / 128), 128, GSMEM_BYTES>>>(
        ffh, w2p, b2, x1, out, NTOK, DMODEL, DFF);
}

// round 15
// speedup vs baseline: 1.8727x; 1.1442x over previous
#include <cuda_runtime.h>
#include <cuda_bf16.h>
#include <cuda_fp16.h>
#include <stdint.h>
#include <math.h>

// ---------------------------------------------------------------------------
// NeuronBloomBlock: B=2, S=2048, D=2048, H=16, HD=128, FF=8192, fp32.
// R15: full-fp16 tensor path. GEMMs fp16 m16n8k16 (R14). Attention now also
//      fp16 m16n8k16: qkv produced as fp16, Q/K staged raw via cp.async
//      (scale folded into ALiBi FMA), V register-packed to k-pair half2,
//      P stored as half2. Halves attention mma count + smem + DRAM stream.
// ---------------------------------------------------------------------------

#define NTOK   4096
#define DMODEL 2048
#define DQKV   6144
#define DFF    8192
#define SEQ    2048
#define NHEAD  16
#define HEADD  128
#define LNEPS  1e-5f

// scratch layout (float units)
#define OFF_X1    ((size_t)0)                    // fp32 [4096][2048]
#define OFF_QKVH  ((size_t)8388608)              // half [4096][6144]
#define OFF_H     ((size_t)20971520)             // half [4096][2048]
#define OFF_ATTNH ((size_t)25165824)             // half [4096][2048]
#define OFF_FFH   ((size_t)29360128)             // half [4096][8192]
#define OFF_WQKVP ((size_t)46137344)             // half2 [1024][6144]
#define OFF_WOP   ((size_t)52428800)             // half2 [1024][2048]
#define OFF_W1P   ((size_t)54525952)             // half2 [1024][8192]
#define OFF_W2P   ((size_t)62914560)             // half2 [4096][2048]
#define SCRATCH_FLOATS ((size_t)71303168)

__device__ float g_scratch[SCRATCH_FLOATS];

// exp(x) for x <= 0 via 2^t, FMA-pipe only (deg-5 poly, rel err ~2e-6).
__device__ __forceinline__ float fast_exp(float x) {
    float t = x * 1.4426950408889634f;
    t = fmaxf(t, -126.0f);
    float r = t + 12582912.0f;
    float i = r - 12582912.0f;
    float f = t - i;
    float p = 0.00133335581f;
    p = fmaf(p, f, 0.00961812910f);
    p = fmaf(p, f, 0.0555041087f);
    p = fmaf(p, f, 0.240226507f);
    p = fmaf(p, f, 0.693147180f);
    p = fmaf(p, f, 1.0f);
    float s = __int_as_float(((int)i + 127) << 23);
    return p * s;
}

__device__ __forceinline__ float gelu_fast(float v) {
    float z = fmaf(0.044715f * v, v * v, v) * 0.7978845608028654f;
    float t = z * 2.8853900817779268f;
    t = fminf(fmaxf(t, -30.0f), 30.0f);
    float r = t + 12582912.0f;
    float i = r - 12582912.0f;
    float f = t - i;
    float p = 0.00133335581f;
    p = fmaf(p, f, 0.00961812910f);
    p = fmaf(p, f, 0.0555041087f);
    p = fmaf(p, f, 0.240226507f);
    p = fmaf(p, f, 0.693147180f);
    p = fmaf(p, f, 1.0f);
    float e2z = p * __int_as_float(((int)i + 127) << 23);
    float th = 1.0f - __fdividef(2.0f, e2z + 1.0f);
    return 0.5f * v * (1.0f + th);
}

// ---------------------------------------------------------------------------
// Weight pack: fp32 [K][N] -> half2 [K/2][N], entry = (k even, k odd).
// ---------------------------------------------------------------------------
__global__ void pack_w_kernel(const float* __restrict__ src, __half2* __restrict__ dst,
                              int K2, int N) {
    int total = K2 * (N >> 2);
    int i = blockIdx.x * blockDim.x + threadIdx.x;
    int stride = gridDim.x * blockDim.x;
    for (; i < total; i += stride) {
        int k2 = i / (N >> 2);
        int nb = (i - k2 * (N >> 2)) << 2;
        const float* r0 = src + (size_t)(2 * k2) * N + nb;
        const float* r1 = r0 + N;
        float4 a = *(const float4*)r0;
        float4 b = *(const float4*)r1;
        __half2* d = dst + (size_t)k2 * N + nb;
        d[0] = __floats2half2_rn(a.x, b.x);
        d[1] = __floats2half2_rn(a.y, b.y);
        d[2] = __floats2half2_rn(a.z, b.z);
        d[3] = __floats2half2_rn(a.w, b.w);
    }
}

// ---------------------------------------------------------------------------
// LayerNorm: one block per row (D=2048), 256 threads; output fp16.
// ---------------------------------------------------------------------------
__global__ void ln_kernel(const float* __restrict__ x, const float* __restrict__ w,
                          const float* __restrict__ bb, __half* __restrict__ out) {
    __shared__ float red[8];
    __shared__ float stat[2];
    int row = blockIdx.x;
    int tid = threadIdx.x;
    const float* xr = x + (size_t)row * DMODEL;

    float4 a = *(const float4*)(xr + tid * 4);
    float4 b = *(const float4*)(xr + 1024 + tid * 4);

    float s = a.x + a.y + a.z + a.w + b.x + b.y + b.z + b.w;
    #pragma unroll
    for (int o = 16; o; o >>= 1) s += __shfl_xor_sync(0xffffffffu, s, o);
    if ((tid & 31) == 0) red[tid >> 5] = s;
    __syncthreads();
    if (tid < 8) {
        float t = red[tid];
        #pragma unroll
        for (int o = 4; o; o >>= 1) t += __shfl_xor_sync(0xffu, t, o);
        if (tid == 0) stat[0] = t;
    }
    __syncthreads();
    float mean = stat[0] * (1.0f / (float)DMODEL);

    float dx0 = a.x - mean, dx1 = a.y - mean, dx2 = a.z - mean, dx3 = a.w - mean;
    float dy0 = b.x - mean, dy1 = b.y - mean, dy2 = b.z - mean, dy3 = b.w - mean;
    float s2 = dx0*dx0 + dx1*dx1 + dx2*dx2 + dx3*dx3
             + dy0*dy0 + dy1*dy1 + dy2*dy2 + dy3*dy3;
    __syncthreads();
    #pragma unroll
    for (int o = 16; o; o >>= 1) s2 += __shfl_xor_sync(0xffffffffu, s2, o);
    if ((tid & 31) == 0) red[tid >> 5] = s2;
    __syncthreads();
    if (tid < 8) {
        float t = red[tid];
        #pragma unroll
        for (int o = 4; o; o >>= 1) t += __shfl_xor_sync(0xffu, t, o);
        if (tid == 0) stat[1] = t;
    }
    __syncthreads();
    float inv = rsqrtf(stat[1] * (1.0f / (float)DMODEL) + LNEPS);

    float4 w0 = *(const float4*)(w + tid * 4);
    float4 w1 = *(const float4*)(w + 1024 + tid * 4);
    float4 g0 = *(const float4*)(bb + tid * 4);
    float4 g1 = *(const float4*)(bb + 1024 + tid * 4);

    __half* orow = out + (size_t)row * DMODEL;
    *(__half2*)(orow + tid * 4) =
        __floats2half2_rn(dx0 * inv * w0.x + g0.x, dx1 * inv * w0.y + g0.y);
    *(__half2*)(orow + tid * 4 + 2) =
        __floats2half2_rn(dx2 * inv * w0.z + g0.z, dx3 * inv * w0.w + g0.w);
    *(__half2*)(orow + 1024 + tid * 4) =
        __floats2half2_rn(dy0 * inv * w1.x + g1.x, dy1 * inv * w1.y + g1.y);
    *(__half2*)(orow + 1024 + tid * 4 + 2) =
        __floats2half2_rn(dy2 * inv * w1.z + g1.z, dy3 * inv * w1.w + g1.w);
}

// ---------------------------------------------------------------------------
// FP16 tensor-core GEMM (R14). Block 128x128, K-tile 32, 128 thr, warp 64x64.
// ---------------------------------------------------------------------------
#define EPI_BIAS      0
#define EPI_BIAS_RES  1
#define EPI_GELU_H    2
#define EPI_BIAS_H    3

__device__ __forceinline__ void mma_f16(float c[4],
        unsigned int a0, unsigned int a1, unsigned int a2, unsigned int a3,
        unsigned int b0, unsigned int b1) {
    asm volatile(
        "mma.sync.aligned.m16n8k16.row.col.f32.f16.f16.f32 "
        "{%0,%1,%2,%3}, {%4,%5,%6,%7}, {%8,%9}, {%0,%1,%2,%3};\n"
        : "+f"(c[0]), "+f"(c[1]), "+f"(c[2]), "+f"(c[3])
        : "r"(a0), "r"(a1), "r"(a2), "r"(a3), "r"(b0), "r"(b1));
}

__device__ __forceinline__ void cp16(void* smem, const void* gmem) {
    unsigned int sa = (unsigned int)__cvta_generic_to_shared(smem);
    asm volatile("cp.async.ca.shared.global [%0], [%1], 16;\n"
                 :: "r"(sa), "l"(gmem));
}
__device__ __forceinline__ void cp_commit() {
    asm volatile("cp.async.commit_group;\n");
}
template<int N>
__device__ __forceinline__ void cp_wait() {
    asm volatile("cp.async.wait_group %0;\n" :: "n"(N));
}

#define APADH 40
#define BPADH 136
#define ASZH (128 * APADH)
#define BSZH (16 * BPADH)
#define GSMEM_BYTES (2 * ASZH * 2 + 2 * BSZH * 4)

template<int EPI>
__global__ __launch_bounds__(128, 2)
void hgemm_kernel(const __half* __restrict__ A, const __half2* __restrict__ Wpk,
                  const float* __restrict__ bias, const float* __restrict__ res,
                  void* __restrict__ Cv, int M, int N, int K) {
    extern __shared__ char smraw[];
    __half*  Ah  = (__half*)smraw;
    __half2* Bh2 = (__half2*)(smraw + 2 * ASZH * 2);

    int tid = threadIdx.x;
    int lane = tid & 31;
    int wid  = tid >> 5;
    int warp_m = wid >> 1;
    int warp_n = wid & 1;
    int bm = blockIdx.y * 128;
    int bn = blockIdx.x * 128;

    int lr = lane >> 2;
    int lc = lane & 3;

    float acc[4][8][4];
    #pragma unroll
    for (int mt = 0; mt < 4; ++mt)
        #pragma unroll
        for (int nt = 0; nt < 8; ++nt)
            #pragma unroll
            for (int r = 0; r < 4; ++r) acc[mt][nt][r] = 0.0f;

    const __half*  Abase = A + (size_t)bm * K;
    const __half2* Wbase = Wpk + bn;

    int ara = tid >> 2, aka = (tid & 3) << 3;
    int brb = tid >> 5, bcb = (tid & 31) << 2;

    auto issue = [&](int stage, int buf) {
        int k0 = stage << 5;
        int k20 = stage << 4;
        #pragma unroll
        for (int u = 0; u < 4; ++u) {
            int r = ara + u * 32;
            cp16(Ah + buf * ASZH + r * APADH + aka, Abase + (size_t)r * K + k0 + aka);
        }
        #pragma unroll
        for (int u = 0; u < 4; ++u) {
            int r2 = brb + u * 4;
            cp16(Bh2 + buf * BSZH + r2 * BPADH + bcb, Wbase + (size_t)(k20 + r2) * N + bcb);
        }
        cp_commit();
    };

    int nk = K >> 5;
    issue(0, 0);
    issue(1, 1);

    for (int kt = 0; kt < nk; ++kt) {
        if (kt == nk - 1) cp_wait<0>(); else cp_wait<1>();
        __syncthreads();

        int cur = kt & 1;
        const __half*  Ac = Ah + cur * ASZH;
        const __half2* Bc = Bh2 + cur * BSZH;

        #pragma unroll
        for (int ks = 0; ks < 2; ++ks) {
            unsigned int af[4][4];
            #pragma unroll
            for (int mt = 0; mt < 4; ++mt) {
                int row = warp_m * 64 + mt * 16 + lr;
                int col = ks * 16 + 2 * lc;
                af[mt][0] = *(const unsigned int*)(Ac + row * APADH + col);
                af[mt][1] = *(const unsigned int*)(Ac + (row + 8) * APADH + col);
                af[mt][2] = *(const unsigned int*)(Ac + row * APADH + col + 8);
                af[mt][3] = *(const unsigned int*)(Ac + (row + 8) * APADH + col + 8);
            }
            unsigned int bf[8][2];
            #pragma unroll
            for (int nt = 0; nt < 8; ++nt) {
                int ncol = warp_n * 64 + nt * 8 + lr;
                int k2r = ks * 8 + lc;
                bf[nt][0] = *(const unsigned int*)(Bc + k2r * BPADH + ncol);
                bf[nt][1] = *(const unsigned int*)(Bc + (k2r + 4) * BPADH + ncol);
            }
            #pragma unroll
            for (int mt = 0; mt < 4; ++mt)
                #pragma unroll
                for (int nt = 0; nt < 8; ++nt)
                    mma_f16(acc[mt][nt], af[mt][0], af[mt][1], af[mt][2], af[mt][3],
                            bf[nt][0], bf[nt][1]);
        }

        if (kt + 2 < nk) {
            __syncthreads();
            issue(kt + 2, cur);
        }
    }

    #pragma unroll
    for (int mt = 0; mt < 4; ++mt) {
        int gr0 = bm + warp_m * 64 + mt * 16 + lr;
        int gr1 = gr0 + 8;
        #pragma unroll
        for (int nt = 0; nt < 8; ++nt) {
            int gc = bn + warp_n * 64 + nt * 8 + (lc << 1);
            float2 bv = *(const float2*)(bias + gc);
            float v0x = acc[mt][nt][0] + bv.x, v0y = acc[mt][nt][1] + bv.y;
            float v1x = acc[mt][nt][2] + bv.x, v1y = acc[mt][nt][3] + bv.y;
            if (EPI == EPI_BIAS_RES) {
                float2 r0 = *(const float2*)(res + (size_t)gr0 * N + gc);
                float2 r1 = *(const float2*)(res + (size_t)gr1 * N + gc);
                v0x += r0.x; v0y += r0.y;
                v1x += r1.x; v1y += r1.y;
            }
            if (EPI == EPI_GELU_H) {
                __half* Ch = (__half*)Cv;
                *(__half2*)(Ch + (size_t)gr0 * N + gc) =
                    __floats2half2_rn(gelu_fast(v0x), gelu_fast(v0y));
                *(__half2*)(Ch + (size_t)gr1 * N + gc) =
                    __floats2half2_rn(gelu_fast(v1x), gelu_fast(v1y));
            } else if (EPI == EPI_BIAS_H) {
                __half* Ch = (__half*)Cv;
                *(__half2*)(Ch + (size_t)gr0 * N + gc) = __floats2half2_rn(v0x, v0y);
                *(__half2*)(Ch + (size_t)gr1 * N + gc) = __floats2half2_rn(v1x, v1y);
            } else {
                float* Cf = (float*)Cv;
                float2 o0; o0.x = v0x; o0.y = v0y;
                float2 o1; o1.x = v1x; o1.y = v1y;
                *(float2*)(Cf + (size_t)gr0 * N + gc) = o0;
                *(float2*)(Cf + (size_t)gr1 * N + gc) = o1;
            }
        }
    }
}

// ---------------------------------------------------------------------------
// FP16 tensor-core flash attention with ALiBi + causal mask.
// qkv fp16 in, fp16 out. Q tile 128 (8 warps x 16 rows), K-block 64.
// S and PV both mma.m16n8k16.f16. Scale folded into ALiBi FMA.
// ---------------------------------------------------------------------------
#define ATQ  128
#define QPH  136        // halfs per Q row
#define KPH  136        // halfs per K row
#define VP2  140        // half2 per Vp k2-row
#define PPH  72         // halfs per P row
#define AT3_SMEM (ATQ*QPH*2 + 64*KPH*2 + 32*VP2*4 + ATQ*PPH*2)

__global__ __launch_bounds__(256)
void attn_kernel(const __half* __restrict__ qkv, __half* __restrict__ out) {
    extern __shared__ char smraw[];
    __half*  Qs = (__half*)smraw;
    __half*  Ks = Qs + ATQ * QPH;
    __half2* Vp = (__half2*)(Ks + 64 * KPH);
    __half*  Ps = (__half*)(Vp + 32 * VP2);

    int tid = threadIdx.x;
    int lane = tid & 31, w = tid >> 5;
    int lr = lane >> 2, lc = lane & 3;
    int qt = gridDim.x - 1 - blockIdx.x;
    int h = blockIdx.y, b = blockIdx.z;
    int q0 = qt * ATQ;

    const float scale = 0.08838834764831845f;   // 1/sqrt(128)
    float slope = exp2f(-0.5f * (float)(h + 1));

    const __half* qbase = qkv + (size_t)b * SEQ * DQKV + (size_t)h * HEADD;
    const __half* kbase = qbase + DMODEL;
    const __half* vbase = qbase + 2 * DMODEL;

    // prologue: stage Q raw via cp.async (128 rows x 128 halfs)
    #pragma unroll
    for (int u = 0; u < 8; ++u) {
        int idx = tid + u * 256;
        int r = idx >> 4, c8 = (idx & 15) << 3;
        cp16(Qs + r * QPH + c8, qbase + (size_t)(q0 + r) * DQKV + c8);
    }
    cp_commit();

    int row0 = q0 + w * 16 + lr;
    int row1 = row0 + 8;
    int wmax = q0 + w * 16 + 15;

    float m0 = -INFINITY, m1 = -INFINITY, l0 = 0.0f, l1 = 0.0f;
    float o[16][4];
    #pragma unroll
    for (int nt = 0; nt < 16; ++nt)
        #pragma unroll
        for (int r = 0; r < 4; ++r) o[nt][r] = 0.0f;

    int nkb = 2 * qt + 2;
    for (int kb = 0; kb < nkb; ++kb) {
        int k0 = kb * 64;
        __syncthreads();    // prev-iter smem reads done
        // K: raw cp.async (64 x 128 halfs)
        #pragma unroll
        for (int u = 0; u < 4; ++u) {
            int idx = tid + u * 256;
            int r = idx >> 4, c8 = (idx & 15) << 3;
            cp16(Ks + r * KPH + c8, kbase + (size_t)(k0 + r) * DQKV + c8);
        }
        cp_commit();
        // V: register k-pair pack (32 k2-rows x 128 d)
        #pragma unroll
        for (int u = 0; u < 2; ++u) {
            int idx = tid + u * 256;
            int k2 = idx >> 4, c8 = (idx & 15) << 3;
            float4 va = *(const float4*)(vbase + (size_t)(k0 + 2 * k2) * DQKV + c8);
            float4 vb = *(const float4*)(vbase + (size_t)(k0 + 2 * k2 + 1) * DQKV + c8);
            const __half* pa = (const __half*)&va;
            const __half* pb = (const __half*)&vb;
            __half2 hh[8];
            #pragma unroll
            for (int j = 0; j < 8; ++j) hh[j] = __halves2half2(pa[j], pb[j]);
            *(float4*)(Vp + k2 * VP2 + c8)     = *(float4*)&hh[0];
            *(float4*)(Vp + k2 * VP2 + c8 + 4) = *(float4*)&hh[4];
        }
        cp_wait<0>();
        __syncthreads();
        if (k0 > wmax) continue;    // fully masked for this warp's rows

        // ---- S = Q @ K^T (fp16, 8 k16 steps) ----
        float sc[8][4];
        #pragma unroll
        for (int nt = 0; nt < 8; ++nt)
            #pragma unroll
            for (int r = 0; r < 4; ++r) sc[nt][r] = 0.0f;

        #pragma unroll
        for (int ks = 0; ks < 8; ++ks) {
            const __half* qrow = Qs + (w * 16 + lr) * QPH + ks * 16 + 2 * lc;
            unsigned int a0 = *(const unsigned int*)(qrow);
            unsigned int a1 = *(const unsigned int*)(qrow + 8 * QPH);
            unsigned int a2 = *(const unsigned int*)(qrow + 8);
            unsigned int a3 = *(const unsigned int*)(qrow + 8 * QPH + 8);
            #pragma unroll
            for (int nt = 0; nt < 8; ++nt) {
                const __half* krow = Ks + (nt * 8 + lr) * KPH + ks * 16 + 2 * lc;
                unsigned int b0 = *(const unsigned int*)(krow);
                unsigned int b1 = *(const unsigned int*)(krow + 8);
                mma_f16(sc[nt], a0, a1, a2, a3, b0, b1);
            }
        }

        // ---- scale + ALiBi + causal + online softmax ----
        float rmax0 = -1e30f, rmax1 = -1e30f;
        #pragma unroll
        for (int nt = 0; nt < 8; ++nt) {
            int gc = k0 + nt * 8 + 2 * lc;
            float al0 = slope * (float)(gc - row0);
            float v0 = fmaf(sc[nt][0], scale, al0);
            float v1 = fmaf(sc[nt][1], scale, al0 + slope);
            if (gc > row0)     v0 = -1e30f;
            if (gc + 1 > row0) v1 = -1e30f;
            float al1 = slope * (float)(gc - row1);
            float u0 = fmaf(sc[nt][2], scale, al1);
            float u1 = fmaf(sc[nt][3], scale, al1 + slope);
            if (gc > row1)     u0 = -1e30f;
            if (gc + 1 > row1) u1 = -1e30f;
            sc[nt][0] = v0; sc[nt][1] = v1; sc[nt][2] = u0; sc[nt][3] = u1;
            rmax0 = fmaxf(rmax0, fmaxf(v0, v1));
            rmax1 = fmaxf(rmax1, fmaxf(u0, u1));
        }
        rmax0 = fmaxf(rmax0, __shfl_xor_sync(0xffffffffu, rmax0, 1));
        rmax0 = fmaxf(rmax0, __shfl_xor_sync(0xffffffffu, rmax0, 2));
        rmax1 = fmaxf(rmax1, __shfl_xor_sync(0xffffffffu, rmax1, 1));
        rmax1 = fmaxf(rmax1, __shfl_xor_sync(0xffffffffu, rmax1, 2));

        float mn0 = fmaxf(m0, rmax0), mn1 = fmaxf(m1, rmax1);
        float alpha0 = fast_exp(m0 - mn0), alpha1 = fast_exp(m1 - mn1);
        m0 = mn0; m1 = mn1;

        __syncwarp();   // lanes done reading Ps from prev iter
        float rs0 = 0.0f, rs1 = 0.0f;
        #pragma unroll
        for (int nt = 0; nt < 8; ++nt) {
            float p0 = fast_exp(sc[nt][0] - mn0);
            float p1 = fast_exp(sc[nt][1] - mn0);
            float p2 = fast_exp(sc[nt][2] - mn1);
            float p3 = fast_exp(sc[nt][3] - mn1);
            rs0 += p0 + p1; rs1 += p2 + p3;
            *(__half2*)(Ps + (w * 16 + lr) * PPH + nt * 8 + 2 * lc) =
                __floats2half2_rn(p0, p1);
            *(__half2*)(Ps + (w * 16 + lr + 8) * PPH + nt * 8 + 2 * lc) =
                __floats2half2_rn(p2, p3);
        }
        rs0 += __shfl_xor_sync(0xffffffffu, rs0, 1);
        rs0 += __shfl_xor_sync(0xffffffffu, rs0, 2);
        rs1 += __shfl_xor_sync(0xffffffffu, rs1, 1);
        rs1 += __shfl_xor_sync(0xffffffffu, rs1, 2);
        l0 = l0 * alpha0 + rs0;
        l1 = l1 * alpha1 + rs1;

        #pragma unroll
        for (int nt = 0; nt < 16; ++nt) {
            o[nt][0] *= alpha0; o[nt][1] *= alpha0;
            o[nt][2] *= alpha1; o[nt][3] *= alpha1;
        }
        __syncwarp();   // Ps writes visible warp-wide

        // ---- O += P @ V (fp16, 4 k16 steps) ----
        #pragma unroll
        for (int ks = 0; ks < 4; ++ks) {
            const __half* prow = Ps + (w * 16 + lr) * PPH + ks * 16 + 2 * lc;
            unsigned int a0 = *(const unsigned int*)(prow);
            unsigned int a1 = *(const unsigned int*)(prow + 8 * PPH);
            unsigned int a2 = *(const unsigned int*)(prow + 8);
            unsigned int a3 = *(const unsigned int*)(prow + 8 * PPH + 8);
            #pragma unroll
            for (int nt = 0; nt < 16; ++nt) {
                const __half2* vrow = Vp + (ks * 8 + lc) * VP2 + nt * 8 + lr;
                unsigned int b0 = *(const unsigned int*)(vrow);
                unsigned int b1 = *(const unsigned int*)(vrow + 4 * VP2);
                mma_f16(o[nt], a0, a1, a2, a3, b0, b1);
            }
        }
    }

    // ---- epilogue (fp16 out) ----
    float inv0 = 1.0f / l0, inv1 = 1.0f / l1;
    size_t or0 = ((size_t)(b * SEQ) + row0) * DMODEL + h * HEADD;
    size_t or1 = or0 + (size_t)8 * DMODEL;
    #pragma unroll
    for (int nt = 0; nt < 16; ++nt) {
        int c = nt * 8 + 2 * lc;
        *(__half2*)(out + or0 + c) = __floats2half2_rn(o[nt][0] * inv0, o[nt][1] * inv0);
        *(__half2*)(out + or1 + c) = __floats2half2_rn(o[nt][2] * inv1, o[nt][3] * inv1);
    }
}

// ---------------------------------------------------------------------------
extern "C" void kernel_launch(void* const* d_in, const int* in_sizes, int n_in,
                              void* d_out, int out_size) {
    const float* x     = (const float*)d_in[0];
    const float* ln1_w = (const float*)d_in[1];
    const float* ln1_b = (const float*)d_in[2];
    const float* wqkv  = (const float*)d_in[3];
    const float* bqkv  = (const float*)d_in[4];
    const float* wo    = (const float*)d_in[5];
    const float* bo    = (const float*)d_in[6];
    const float* ln2_w = (const float*)d_in[7];
    const float* ln2_b = (const float*)d_in[8];
    const float* w1    = (const float*)d_in[9];
    const float* b1    = (const float*)d_in[10];
    const float* w2    = (const float*)d_in[11];
    const float* b2    = (const float*)d_in[12];
    float* out = (float*)d_out;

    float* base = nullptr;
    cudaGetSymbolAddress((void**)&base, g_scratch);
    float*   x1    = base + OFF_X1;
    __half*  qkvh  = (__half*)(base + OFF_QKVH);
    __half*  h     = (__half*)(base + OFF_H);
    __half*  attnh = (__half*)(base + OFF_ATTNH);
    __half*  ffh   = (__half*)(base + OFF_FFH);
    __half2* wqkvp = (__half2*)(base + OFF_WQKVP);
    __half2* wop   = (__half2*)(base + OFF_WOP);
    __half2* w1p   = (__half2*)(base + OFF_W1P);
    __half2* w2p   = (__half2*)(base + OFF_W2P);

    cudaFuncSetAttribute(attn_kernel, cudaFuncAttributeMaxDynamicSharedMemorySize, AT3_SMEM);
    cudaFuncSetAttribute(hgemm_kernel<EPI_BIAS_H>,
                         cudaFuncAttributeMaxDynamicSharedMemorySize, GSMEM_BYTES);
    cudaFuncSetAttribute(hgemm_kernel<EPI_BIAS_RES>,
                         cudaFuncAttributeMaxDynamicSharedMemorySize, GSMEM_BYTES);
    cudaFuncSetAttribute(hgemm_kernel<EPI_GELU_H>,
                         cudaFuncAttributeMaxDynamicSharedMemorySize, GSMEM_BYTES);

    // 0. pack weights to k-pair half2
    pack_w_kernel<<<2048, 256>>>(wqkv, wqkvp, DMODEL / 2, DQKV);
    pack_w_kernel<<<1024, 256>>>(wo,   wop,   DMODEL / 2, DMODEL);
    pack_w_kernel<<<2048, 256>>>(w1,   w1p,   DMODEL / 2, DFF);
    pack_w_kernel<<<2048, 256>>>(w2,   w2p,   DFF / 2,    DMODEL);

    // 1. h = LN1(x)  (fp16 out)
    ln_kernel<<<NTOK, 256>>>(x, ln1_w, ln1_b, h);
    // 2. qkv = h @ wqkv + bqkv  (fp16 out)
    hgemm_kernel<EPI_BIAS_H><<<dim3(DQKV / 128, NTOK / 128), 128, GSMEM_BYTES>>>(
        h, wqkvp, bqkv, nullptr, qkvh, NTOK, DQKV, DMODEL);
    // 3. attention (fp16 in, fp16 out)
    attn_kernel<<<dim3(SEQ / ATQ, NHEAD, 2), 256, AT3_SMEM>>>(qkvh, attnh);
    // 4. x1 = x + attn @ wo + bo  (fp32 out)
    hgemm_kernel<EPI_BIAS_RES><<<dim3(DMODEL / 128, NTOK / 128), 128, GSMEM_BYTES>>>(
        attnh, wop, bo, x, x1, NTOK, DMODEL, DMODEL);
    // 5. h = LN2(x1)  (fp16 out)
    ln_kernel<<<NTOK, 256>>>(x1, ln2_w, ln2_b, h);
    // 6. ff = gelu(h @ w1 + b1)  (fp16 out)
    hgemm_kernel<EPI_GELU_H><<<dim3(DFF / 128, NTOK / 128), 128, GSMEM_BYTES>>>(
        h, w1p, b1, nullptr, ffh, NTOK, DFF, DMODEL);
    // 7. out = x1 + ff @ w2 + b2  (fp32 out)
    hgemm_kernel<EPI_BIAS_RES><<<dim3(DMODEL / 128, NTOK / 128), 128, GSMEM_BYTES>>>(
        ffh, w2p, b2, x1, out, NTOK, DMODEL, DFF);
}

// round 16
// speedup vs baseline: 1.8994x; 1.0143x over previous
#include <cuda_runtime.h>
#include <cuda_bf16.h>
#include <cuda_fp16.h>
#include <stdint.h>
#include <math.h>

// ---------------------------------------------------------------------------
// NeuronBloomBlock: B=2, S=2048, D=2048, H=16, HD=128, FF=8192, fp32.
// R16: R15 + hgemm mainloop converted to 3-stage cp.async ring with a single
//      __syncthreads per K-iteration (barrier count halved, 2 groups always
//      in flight during compute). Attention/LN/pack unchanged.
// ---------------------------------------------------------------------------

#define NTOK   4096
#define DMODEL 2048
#define DQKV   6144
#define DFF    8192
#define SEQ    2048
#define NHEAD  16
#define HEADD  128
#define LNEPS  1e-5f

// scratch layout (float units)
#define OFF_X1    ((size_t)0)                    // fp32 [4096][2048]
#define OFF_QKVH  ((size_t)8388608)              // half [4096][6144]
#define OFF_H     ((size_t)20971520)             // half [4096][2048]
#define OFF_ATTNH ((size_t)25165824)             // half [4096][2048]
#define OFF_FFH   ((size_t)29360128)             // half [4096][8192]
#define OFF_WQKVP ((size_t)46137344)             // half2 [1024][6144]
#define OFF_WOP   ((size_t)52428800)             // half2 [1024][2048]
#define OFF_W1P   ((size_t)54525952)             // half2 [1024][8192]
#define OFF_W2P   ((size_t)62914560)             // half2 [4096][2048]
#define SCRATCH_FLOATS ((size_t)71303168)

__device__ float g_scratch[SCRATCH_FLOATS];

// exp(x) for x <= 0 via 2^t, FMA-pipe only (deg-5 poly, rel err ~2e-6).
__device__ __forceinline__ float fast_exp(float x) {
    float t = x * 1.4426950408889634f;
    t = fmaxf(t, -126.0f);
    float r = t + 12582912.0f;
    float i = r - 12582912.0f;
    float f = t - i;
    float p = 0.00133335581f;
    p = fmaf(p, f, 0.00961812910f);
    p = fmaf(p, f, 0.0555041087f);
    p = fmaf(p, f, 0.240226507f);
    p = fmaf(p, f, 0.693147180f);
    p = fmaf(p, f, 1.0f);
    float s = __int_as_float(((int)i + 127) << 23);
    return p * s;
}

__device__ __forceinline__ float gelu_fast(float v) {
    float z = fmaf(0.044715f * v, v * v, v) * 0.7978845608028654f;
    float t = z * 2.8853900817779268f;
    t = fminf(fmaxf(t, -30.0f), 30.0f);
    float r = t + 12582912.0f;
    float i = r - 12582912.0f;
    float f = t - i;
    float p = 0.00133335581f;
    p = fmaf(p, f, 0.00961812910f);
    p = fmaf(p, f, 0.0555041087f);
    p = fmaf(p, f, 0.240226507f);
    p = fmaf(p, f, 0.693147180f);
    p = fmaf(p, f, 1.0f);
    float e2z = p * __int_as_float(((int)i + 127) << 23);
    float th = 1.0f - __fdividef(2.0f, e2z + 1.0f);
    return 0.5f * v * (1.0f + th);
}

// ---------------------------------------------------------------------------
// Weight pack: fp32 [K][N] -> half2 [K/2][N], entry = (k even, k odd).
// ---------------------------------------------------------------------------
__global__ void pack_w_kernel(const float* __restrict__ src, __half2* __restrict__ dst,
                              int K2, int N) {
    int total = K2 * (N >> 2);
    int i = blockIdx.x * blockDim.x + threadIdx.x;
    int stride = gridDim.x * blockDim.x;
    for (; i < total; i += stride) {
        int k2 = i / (N >> 2);
        int nb = (i - k2 * (N >> 2)) << 2;
        const float* r0 = src + (size_t)(2 * k2) * N + nb;
        const float* r1 = r0 + N;
        float4 a = *(const float4*)r0;
        float4 b = *(const float4*)r1;
        __half2* d = dst + (size_t)k2 * N + nb;
        d[0] = __floats2half2_rn(a.x, b.x);
        d[1] = __floats2half2_rn(a.y, b.y);
        d[2] = __floats2half2_rn(a.z, b.z);
        d[3] = __floats2half2_rn(a.w, b.w);
    }
}

// ---------------------------------------------------------------------------
// LayerNorm: one block per row (D=2048), 256 threads; output fp16.
// ---------------------------------------------------------------------------
__global__ void ln_kernel(const float* __restrict__ x, const float* __restrict__ w,
                          const float* __restrict__ bb, __half* __restrict__ out) {
    __shared__ float red[8];
    __shared__ float stat[2];
    int row = blockIdx.x;
    int tid = threadIdx.x;
    const float* xr = x + (size_t)row * DMODEL;

    float4 a = *(const float4*)(xr + tid * 4);
    float4 b = *(const float4*)(xr + 1024 + tid * 4);

    float s = a.x + a.y + a.z + a.w + b.x + b.y + b.z + b.w;
    #pragma unroll
    for (int o = 16; o; o >>= 1) s += __shfl_xor_sync(0xffffffffu, s, o);
    if ((tid & 31) == 0) red[tid >> 5] = s;
    __syncthreads();
    if (tid < 8) {
        float t = red[tid];
        #pragma unroll
        for (int o = 4; o; o >>= 1) t += __shfl_xor_sync(0xffu, t, o);
        if (tid == 0) stat[0] = t;
    }
    __syncthreads();
    float mean = stat[0] * (1.0f / (float)DMODEL);

    float dx0 = a.x - mean, dx1 = a.y - mean, dx2 = a.z - mean, dx3 = a.w - mean;
    float dy0 = b.x - mean, dy1 = b.y - mean, dy2 = b.z - mean, dy3 = b.w - mean;
    float s2 = dx0*dx0 + dx1*dx1 + dx2*dx2 + dx3*dx3
             + dy0*dy0 + dy1*dy1 + dy2*dy2 + dy3*dy3;
    __syncthreads();
    #pragma unroll
    for (int o = 16; o; o >>= 1) s2 += __shfl_xor_sync(0xffffffffu, s2, o);
    if ((tid & 31) == 0) red[tid >> 5] = s2;
    __syncthreads();
    if (tid < 8) {
        float t = red[tid];
        #pragma unroll
        for (int o = 4; o; o >>= 1) t += __shfl_xor_sync(0xffu, t, o);
        if (tid == 0) stat[1] = t;
    }
    __syncthreads();
    float inv = rsqrtf(stat[1] * (1.0f / (float)DMODEL) + LNEPS);

    float4 w0 = *(const float4*)(w + tid * 4);
    float4 w1 = *(const float4*)(w + 1024 + tid * 4);
    float4 g0 = *(const float4*)(bb + tid * 4);
    float4 g1 = *(const float4*)(bb + 1024 + tid * 4);

    __half* orow = out + (size_t)row * DMODEL;
    *(__half2*)(orow + tid * 4) =
        __floats2half2_rn(dx0 * inv * w0.x + g0.x, dx1 * inv * w0.y + g0.y);
    *(__half2*)(orow + tid * 4 + 2) =
        __floats2half2_rn(dx2 * inv * w0.z + g0.z, dx3 * inv * w0.w + g0.w);
    *(__half2*)(orow + 1024 + tid * 4) =
        __floats2half2_rn(dy0 * inv * w1.x + g1.x, dy1 * inv * w1.y + g1.y);
    *(__half2*)(orow + 1024 + tid * 4 + 2) =
        __floats2half2_rn(dy2 * inv * w1.z + g1.z, dy3 * inv * w1.w + g1.w);
}

// ---------------------------------------------------------------------------
// FP16 tensor-core GEMM, 3-stage cp.async ring, 1 barrier per K-iter.
// Block 128x128, K-tile 32, 128 threads, warp tile 64x64.
// ---------------------------------------------------------------------------
#define EPI_BIAS      0
#define EPI_BIAS_RES  1
#define EPI_GELU_H    2
#define EPI_BIAS_H    3

__device__ __forceinline__ void mma_f16(float c[4],
        unsigned int a0, unsigned int a1, unsigned int a2, unsigned int a3,
        unsigned int b0, unsigned int b1) {
    asm volatile(
        "mma.sync.aligned.m16n8k16.row.col.f32.f16.f16.f32 "
        "{%0,%1,%2,%3}, {%4,%5,%6,%7}, {%8,%9}, {%0,%1,%2,%3};\n"
        : "+f"(c[0]), "+f"(c[1]), "+f"(c[2]), "+f"(c[3])
        : "r"(a0), "r"(a1), "r"(a2), "r"(a3), "r"(b0), "r"(b1));
}

__device__ __forceinline__ void cp16(void* smem, const void* gmem) {
    unsigned int sa = (unsigned int)__cvta_generic_to_shared(smem);
    asm volatile("cp.async.ca.shared.global [%0], [%1], 16;\n"
                 :: "r"(sa), "l"(gmem));
}
__device__ __forceinline__ void cp_commit() {
    asm volatile("cp.async.commit_group;\n");
}
template<int N>
__device__ __forceinline__ void cp_wait() {
    asm volatile("cp.async.wait_group %0;\n" :: "n"(N));
}

#define APADH 40
#define BPADH 136
#define ASZH (128 * APADH)            // halfs per A stage
#define BSZH (16 * BPADH)             // half2 per B stage
#define GSMEM_BYTES (3 * ASZH * 2 + 3 * BSZH * 4)   // 56832

template<int EPI>
__global__ __launch_bounds__(128, 2)
void hgemm_kernel(const __half* __restrict__ A, const __half2* __restrict__ Wpk,
                  const float* __restrict__ bias, const float* __restrict__ res,
                  void* __restrict__ Cv, int M, int N, int K) {
    extern __shared__ char smraw[];
    __half*  Ah  = (__half*)smraw;                      // [3][128][APADH]
    __half2* Bh2 = (__half2*)(smraw + 3 * ASZH * 2);    // [3][16][BPADH]

    int tid = threadIdx.x;
    int lane = tid & 31;
    int wid  = tid >> 5;
    int warp_m = wid >> 1;
    int warp_n = wid & 1;
    int bm = blockIdx.y * 128;
    int bn = blockIdx.x * 128;

    int lr = lane >> 2;
    int lc = lane & 3;

    float acc[4][8][4];
    #pragma unroll
    for (int mt = 0; mt < 4; ++mt)
        #pragma unroll
        for (int nt = 0; nt < 8; ++nt)
            #pragma unroll
            for (int r = 0; r < 4; ++r) acc[mt][nt][r] = 0.0f;

    const __half*  Abase = A + (size_t)bm * K;
    const __half2* Wbase = Wpk + bn;

    int ara = tid >> 2, aka = (tid & 3) << 3;
    int brb = tid >> 5, bcb = (tid & 31) << 2;

    auto issue = [&](int stage, int buf) {
        int k0 = stage << 5;
        int k20 = stage << 4;
        #pragma unroll
        for (int u = 0; u < 4; ++u) {
            int r = ara + u * 32;
            cp16(Ah + buf * ASZH + r * APADH + aka, Abase + (size_t)r * K + k0 + aka);
        }
        #pragma unroll
        for (int u = 0; u < 4; ++u) {
            int r2 = brb + u * 4;
            cp16(Bh2 + buf * BSZH + r2 * BPADH + bcb, Wbase + (size_t)(k20 + r2) * N + bcb);
        }
        cp_commit();
    };

    int nk = K >> 5;
    issue(0, 0);
    issue(1, 1);

    int buf = 0;            // buffer of stage kt
    for (int kt = 0; kt < nk; ++kt) {
        if (kt == nk - 1) cp_wait<0>(); else cp_wait<1>();
        __syncthreads();    // stage kt visible to all; prior reads of buf(kt+2)%3 done

        // refill the ring: stage kt+2 into the buffer consumed at kt-1
        if (kt + 2 < nk) {
            int nbuf = buf + 2; if (nbuf >= 3) nbuf -= 3;
            issue(kt + 2, nbuf);
        }

        const __half*  Ac = Ah + buf * ASZH;
        const __half2* Bc = Bh2 + buf * BSZH;

        #pragma unroll
        for (int ks = 0; ks < 2; ++ks) {
            unsigned int af[4][4];
            #pragma unroll
            for (int mt = 0; mt < 4; ++mt) {
                int row = warp_m * 64 + mt * 16 + lr;
                int col = ks * 16 + 2 * lc;
                af[mt][0] = *(const unsigned int*)(Ac + row * APADH + col);
                af[mt][1] = *(const unsigned int*)(Ac + (row + 8) * APADH + col);
                af[mt][2] = *(const unsigned int*)(Ac + row * APADH + col + 8);
                af[mt][3] = *(const unsigned int*)(Ac + (row + 8) * APADH + col + 8);
            }
            unsigned int bf[8][2];
            #pragma unroll
            for (int nt = 0; nt < 8; ++nt) {
                int ncol = warp_n * 64 + nt * 8 + lr;
                int k2r = ks * 8 + lc;
                bf[nt][0] = *(const unsigned int*)(Bc + k2r * BPADH + ncol);
                bf[nt][1] = *(const unsigned int*)(Bc + (k2r + 4) * BPADH + ncol);
            }
            #pragma unroll
            for (int mt = 0; mt < 4; ++mt)
                #pragma unroll
                for (int nt = 0; nt < 8; ++nt)
                    mma_f16(acc[mt][nt], af[mt][0], af[mt][1], af[mt][2], af[mt][3],
                            bf[nt][0], bf[nt][1]);
        }

        if (++buf == 3) buf = 0;
    }

    #pragma unroll
    for (int mt = 0; mt < 4; ++mt) {
        int gr0 = bm + warp_m * 64 + mt * 16 + lr;
        int gr1 = gr0 + 8;
        #pragma unroll
        for (int nt = 0; nt < 8; ++nt) {
            int gc = bn + warp_n * 64 + nt * 8 + (lc << 1);
            float2 bv = *(const float2*)(bias + gc);
            float v0x = acc[mt][nt][0] + bv.x, v0y = acc[mt][nt][1] + bv.y;
            float v1x = acc[mt][nt][2] + bv.x, v1y = acc[mt][nt][3] + bv.y;
            if (EPI == EPI_BIAS_RES) {
                float2 r0 = *(const float2*)(res + (size_t)gr0 * N + gc);
                float2 r1 = *(const float2*)(res + (size_t)gr1 * N + gc);
                v0x += r0.x; v0y += r0.y;
                v1x += r1.x; v1y += r1.y;
            }
            if (EPI == EPI_GELU_H) {
                __half* Ch = (__half*)Cv;
                *(__half2*)(Ch + (size_t)gr0 * N + gc) =
                    __floats2half2_rn(gelu_fast(v0x), gelu_fast(v0y));
                *(__half2*)(Ch + (size_t)gr1 * N + gc) =
                    __floats2half2_rn(gelu_fast(v1x), gelu_fast(v1y));
            } else if (EPI == EPI_BIAS_H) {
                __half* Ch = (__half*)Cv;
                *(__half2*)(Ch + (size_t)gr0 * N + gc) = __floats2half2_rn(v0x, v0y);
                *(__half2*)(Ch + (size_t)gr1 * N + gc) = __floats2half2_rn(v1x, v1y);
            } else {
                float* Cf = (float*)Cv;
                float2 o0; o0.x = v0x; o0.y = v0y;
                float2 o1; o1.x = v1x; o1.y = v1y;
                *(float2*)(Cf + (size_t)gr0 * N + gc) = o0;
                *(float2*)(Cf + (size_t)gr1 * N + gc) = o1;
            }
        }
    }
}

// ---------------------------------------------------------------------------
// FP16 tensor-core flash attention with ALiBi + causal mask. (R15)
// ---------------------------------------------------------------------------
#define ATQ  128
#define QPH  136
#define KPH  136
#define VP2  140
#define PPH  72
#define AT3_SMEM (ATQ*QPH*2 + 64*KPH*2 + 32*VP2*4 + ATQ*PPH*2)

__global__ __launch_bounds__(256)
void attn_kernel(const __half* __restrict__ qkv, __half* __restrict__ out) {
    extern __shared__ char smraw[];
    __half*  Qs = (__half*)smraw;
    __half*  Ks = Qs + ATQ * QPH;
    __half2* Vp = (__half2*)(Ks + 64 * KPH);
    __half*  Ps = (__half*)(Vp + 32 * VP2);

    int tid = threadIdx.x;
    int lane = tid & 31, w = tid >> 5;
    int lr = lane >> 2, lc = lane & 3;
    int qt = gridDim.x - 1 - blockIdx.x;
    int h = blockIdx.y, b = blockIdx.z;
    int q0 = qt * ATQ;

    const float scale = 0.08838834764831845f;
    float slope = exp2f(-0.5f * (float)(h + 1));

    const __half* qbase = qkv + (size_t)b * SEQ * DQKV + (size_t)h * HEADD;
    const __half* kbase = qbase + DMODEL;
    const __half* vbase = qbase + 2 * DMODEL;

    #pragma unroll
    for (int u = 0; u < 8; ++u) {
        int idx = tid + u * 256;
        int r = idx >> 4, c8 = (idx & 15) << 3;
        cp16(Qs + r * QPH + c8, qbase + (size_t)(q0 + r) * DQKV + c8);
    }
    cp_commit();

    int row0 = q0 + w * 16 + lr;
    int row1 = row0 + 8;
    int wmax = q0 + w * 16 + 15;

    float m0 = -INFINITY, m1 = -INFINITY, l0 = 0.0f, l1 = 0.0f;
    float o[16][4];
    #pragma unroll
    for (int nt = 0; nt < 16; ++nt)
        #pragma unroll
        for (int r = 0; r < 4; ++r) o[nt][r] = 0.0f;

    int nkb = 2 * qt + 2;
    for (int kb = 0; kb < nkb; ++kb) {
        int k0 = kb * 64;
        __syncthreads();
        #pragma unroll
        for (int u = 0; u < 4; ++u) {
            int idx = tid + u * 256;
            int r = idx >> 4, c8 = (idx & 15) << 3;
            cp16(Ks + r * KPH + c8, kbase + (size_t)(k0 + r) * DQKV + c8);
        }
        cp_commit();
        #pragma unroll
        for (int u = 0; u < 2; ++u) {
            int idx = tid + u * 256;
            int k2 = idx >> 4, c8 = (idx & 15) << 3;
            float4 va = *(const float4*)(vbase + (size_t)(k0 + 2 * k2) * DQKV + c8);
            float4 vb = *(const float4*)(vbase + (size_t)(k0 + 2 * k2 + 1) * DQKV + c8);
            const __half* pa = (const __half*)&va;
            const __half* pb = (const __half*)&vb;
            __half2 hh[8];
            #pragma unroll
            for (int j = 0; j < 8; ++j) hh[j] = __halves2half2(pa[j], pb[j]);
            *(float4*)(Vp + k2 * VP2 + c8)     = *(float4*)&hh[0];
            *(float4*)(Vp + k2 * VP2 + c8 + 4) = *(float4*)&hh[4];
        }
        cp_wait<0>();
        __syncthreads();
        if (k0 > wmax) continue;

        float sc[8][4];
        #pragma unroll
        for (int nt = 0; nt < 8; ++nt)
            #pragma unroll
            for (int r = 0; r < 4; ++r) sc[nt][r] = 0.0f;

        #pragma unroll
        for (int ks = 0; ks < 8; ++ks) {
            const __half* qrow = Qs + (w * 16 + lr) * QPH + ks * 16 + 2 * lc;
            unsigned int a0 = *(const unsigned int*)(qrow);
            unsigned int a1 = *(const unsigned int*)(qrow + 8 * QPH);
            unsigned int a2 = *(const unsigned int*)(qrow + 8);
            unsigned int a3 = *(const unsigned int*)(qrow + 8 * QPH + 8);
            #pragma unroll
            for (int nt = 0; nt < 8; ++nt) {
                const __half* krow = Ks + (nt * 8 + lr) * KPH + ks * 16 + 2 * lc;
                unsigned int b0 = *(const unsigned int*)(krow);
                unsigned int b1 = *(const unsigned int*)(krow + 8);
                mma_f16(sc[nt], a0, a1, a2, a3, b0, b1);
            }
        }

        float rmax0 = -1e30f, rmax1 = -1e30f;
        #pragma unroll
        for (int nt = 0; nt < 8; ++nt) {
            int gc = k0 + nt * 8 + 2 * lc;
            float al0 = slope * (float)(gc - row0);
            float v0 = fmaf(sc[nt][0], scale, al0);
            float v1 = fmaf(sc[nt][1], scale, al0 + slope);
            if (gc > row0)     v0 = -1e30f;
            if (gc + 1 > row0) v1 = -1e30f;
            float al1 = slope * (float)(gc - row1);
            float u0 = fmaf(sc[nt][2], scale, al1);
            float u1 = fmaf(sc[nt][3], scale, al1 + slope);
            if (gc > row1)     u0 = -1e30f;
            if (gc + 1 > row1) u1 = -1e30f;
            sc[nt][0] = v0; sc[nt][1] = v1; sc[nt][2] = u0; sc[nt][3] = u1;
            rmax0 = fmaxf(rmax0, fmaxf(v0, v1));
            rmax1 = fmaxf(rmax1, fmaxf(u0, u1));
        }
        rmax0 = fmaxf(rmax0, __shfl_xor_sync(0xffffffffu, rmax0, 1));
        rmax0 = fmaxf(rmax0, __shfl_xor_sync(0xffffffffu, rmax0, 2));
        rmax1 = fmaxf(rmax1, __shfl_xor_sync(0xffffffffu, rmax1, 1));
        rmax1 = fmaxf(rmax1, __shfl_xor_sync(0xffffffffu, rmax1, 2));

        float mn0 = fmaxf(m0, rmax0), mn1 = fmaxf(m1, rmax1);
        float alpha0 = fast_exp(m0 - mn0), alpha1 = fast_exp(m1 - mn1);
        m0 = mn0; m1 = mn1;

        __syncwarp();
        float rs0 = 0.0f, rs1 = 0.0f;
        #pragma unroll
        for (int nt = 0; nt < 8; ++nt) {
            float p0 = fast_exp(sc[nt][0] - mn0);
            float p1 = fast_exp(sc[nt][1] - mn0);
            float p2 = fast_exp(sc[nt][2] - mn1);
            float p3 = fast_exp(sc[nt][3] - mn1);
            rs0 += p0 + p1; rs1 += p2 + p3;
            *(__half2*)(Ps + (w * 16 + lr) * PPH + nt * 8 + 2 * lc) =
                __floats2half2_rn(p0, p1);
            *(__half2*)(Ps + (w * 16 + lr + 8) * PPH + nt * 8 + 2 * lc) =
                __floats2half2_rn(p2, p3);
        }
        rs0 += __shfl_xor_sync(0xffffffffu, rs0, 1);
        rs0 += __shfl_xor_sync(0xffffffffu, rs0, 2);
        rs1 += __shfl_xor_sync(0xffffffffu, rs1, 1);
        rs1 += __shfl_xor_sync(0xffffffffu, rs1, 2);
        l0 = l0 * alpha0 + rs0;
        l1 = l1 * alpha1 + rs1;

        #pragma unroll
        for (int nt = 0; nt < 16; ++nt) {
            o[nt][0] *= alpha0; o[nt][1] *= alpha0;
            o[nt][2] *= alpha1; o[nt][3] *= alpha1;
        }
        __syncwarp();

        #pragma unroll
        for (int ks = 0; ks < 4; ++ks) {
            const __half* prow = Ps + (w * 16 + lr) * PPH + ks * 16 + 2 * lc;
            unsigned int a0 = *(const unsigned int*)(prow);
            unsigned int a1 = *(const unsigned int*)(prow + 8 * PPH);
            unsigned int a2 = *(const unsigned int*)(prow + 8);
            unsigned int a3 = *(const unsigned int*)(prow + 8 * PPH + 8);
            #pragma unroll
            for (int nt = 0; nt < 16; ++nt) {
                const __half2* vrow = Vp + (ks * 8 + lc) * VP2 + nt * 8 + lr;
                unsigned int b0 = *(const unsigned int*)(vrow);
                unsigned int b1 = *(const unsigned int*)(vrow + 4 * VP2);
                mma_f16(o[nt], a0, a1, a2, a3, b0, b1);
            }
        }
    }

    float inv0 = 1.0f / l0, inv1 = 1.0f / l1;
    size_t or0 = ((size_t)(b * SEQ) + row0) * DMODEL + h * HEADD;
    size_t or1 = or0 + (size_t)8 * DMODEL;
    #pragma unroll
    for (int nt = 0; nt < 16; ++nt) {
        int c = nt * 8 + 2 * lc;
        *(__half2*)(out + or0 + c) = __floats2half2_rn(o[nt][0] * inv0, o[nt][1] * inv0);
        *(__half2*)(out + or1 + c) = __floats2half2_rn(o[nt][2] * inv1, o[nt][3] * inv1);
    }
}

// ---------------------------------------------------------------------------
extern "C" void kernel_launch(void* const* d_in, const int* in_sizes, int n_in,
                              void* d_out, int out_size) {
    const float* x     = (const float*)d_in[0];
    const float* ln1_w = (const float*)d_in[1];
    const float* ln1_b = (const float*)d_in[2];
    const float* wqkv  = (const float*)d_in[3];
    const float* bqkv  = (const float*)d_in[4];
    const float* wo    = (const float*)d_in[5];
    const float* bo    = (const float*)d_in[6];
    const float* ln2_w = (const float*)d_in[7];
    const float* ln2_b = (const float*)d_in[8];
    const float* w1    = (const float*)d_in[9];
    const float* b1    = (const float*)d_in[10];
    const float* w2    = (const float*)d_in[11];
    const float* b2    = (const float*)d_in[12];
    float* out = (float*)d_out;

    float* base = nullptr;
    cudaGetSymbolAddress((void**)&base, g_scratch);
    float*   x1    = base + OFF_X1;
    __half*  qkvh  = (__half*)(base + OFF_QKVH);
    __half*  h     = (__half*)(base + OFF_H);
    __half*  attnh = (__half*)(base + OFF_ATTNH);
    __half*  ffh   = (__half*)(base + OFF_FFH);
    __half2* wqkvp = (__half2*)(base + OFF_WQKVP);
    __half2* wop   = (__half2*)(base + OFF_WOP);
    __half2* w1p   = (__half2*)(base + OFF_W1P);
    __half2* w2p   = (__half2*)(base + OFF_W2P);

    cudaFuncSetAttribute(attn_kernel, cudaFuncAttributeMaxDynamicSharedMemorySize, AT3_SMEM);
    cudaFuncSetAttribute(hgemm_kernel<EPI_BIAS_H>,
                         cudaFuncAttributeMaxDynamicSharedMemorySize, GSMEM_BYTES);
    cudaFuncSetAttribute(hgemm_kernel<EPI_BIAS_RES>,
                         cudaFuncAttributeMaxDynamicSharedMemorySize, GSMEM_BYTES);
    cudaFuncSetAttribute(hgemm_kernel<EPI_GELU_H>,
                         cudaFuncAttributeMaxDynamicSharedMemorySize, GSMEM_BYTES);

    // 0. pack weights to k-pair half2
    pack_w_kernel<<<2048, 256>>>(wqkv, wqkvp, DMODEL / 2, DQKV);
    pack_w_kernel<<<1024, 256>>>(wo,   wop,   DMODEL / 2, DMODEL);
    pack_w_kernel<<<2048, 256>>>(w1,   w1p,   DMODEL / 2, DFF);
    pack_w_kernel<<<2048, 256>>>(w2,   w2p,   DFF / 2,    DMODEL);

    // 1. h = LN1(x)  (fp16 out)
    ln_kernel<<<NTOK, 256>>>(x, ln1_w, ln1_b, h);
    // 2. qkv = h @ wqkv + bqkv  (fp16 out)
    hgemm_kernel<EPI_BIAS_H><<<dim3(DQKV / 128, NTOK / 128), 128, GSMEM_BYTES>>>(
        h, wqkvp, bqkv, nullptr, qkvh, NTOK, DQKV, DMODEL);
    // 3. attention (fp16 in/out)
    attn_kernel<<<dim3(SEQ / ATQ, NHEAD, 2), 256, AT3_SMEM>>>(qkvh, attnh);
    // 4. x1 = x + attn @ wo + bo  (fp32 out)
    hgemm_kernel<EPI_BIAS_RES><<<dim3(DMODEL / 128, NTOK / 128), 128, GSMEM_BYTES>>>(
        attnh, wop, bo, x, x1, NTOK, DMODEL, DMODEL);
    // 5. h = LN2(x1)  (fp16 out)
    ln_kernel<<<NTOK, 256>>>(x1, ln2_w, ln2_b, h);
    // 6. ff = gelu(h @ w1 + b1)  (fp16 out)
    hgemm_kernel<EPI_GELU_H><<<dim3(DFF / 128, NTOK / 128), 128, GSMEM_BYTES>>>(
        h, w1p, b1, nullptr, ffh, NTOK, DFF, DMODEL);
    // 7. out = x1 + ff @ w2 + b2  (fp32 out)
    hgemm_kernel<EPI_BIAS_RES><<<dim3(DMODEL / 128, NTOK / 128), 128, GSMEM_BYTES>>>(
        ffh, w2p, b2, x1, out, NTOK, DMODEL, DFF);
}